// round 1
// baseline (speedup 1.0000x reference)
#include <cuda_runtime.h>

// ---------------- problem constants ----------------
#define B_    16
#define C_    128
#define T_    16384
#define W_    2048      // wordnum = T/patch
#define P_    8
#define MIDC_ 128
#define CP_   1024      // MIDC * P

// ---------------- scratch (device globals; allocation-free rule) ----------------
__device__ float g_q [(size_t)B_ * W_ * CP_];   // softmaxed Q   [b][w][i]
__device__ float g_k [(size_t)B_ * W_ * CP_];   // raw K + mask  [b][w][i]
__device__ float g_v [(size_t)B_ * W_ * CP_];   // raw V         [b][w][i]
__device__ float g_kv[(size_t)B_ * CP_ * CP_];  // K^T V         [b][i][j]
__device__ float g_at[(size_t)B_ * MIDC_ * T_]; // attn out      [b][m][t]
__device__ float g_m [B_ * CP_];                // column max of K
__device__ float g_rs[B_ * CP_];                // 1 / column sum(exp)

__device__ __forceinline__ void fma4(float4 &c, float a, const float4 &b) {
    c.x = fmaf(a, b.x, c.x);
    c.y = fmaf(a, b.y, c.y);
    c.z = fmaf(a, b.z, c.z);
    c.w = fmaf(a, b.w, c.w);
}

// =====================================================================
// Kernel A: Q grouped conv (5 taps over w, groups=4) + fused softmax over i
// block = (b, 4 consecutive w), 256 threads; thread: oc = tid&127, p0 = (tid>>7)*4
// =====================================================================
#define KQ_W  4
__global__ __launch_bounds__(256, 1)
void kQ(const float* __restrict__ cond,
        const float* __restrict__ wQ, const float* __restrict__ bQ)
{
    extern __shared__ float sm[];
    float* wq_s = sm;                 // 128 * 161 (padded rows, conflict-free)
    float* cs   = sm + 128 * 161;     // 128 ic * 64 t  (w0-2 .. w0+5)
    float* red  = cs + 128 * 64;      // 8 warp partials

    const int tid = threadIdx.x;
    const int b   = blockIdx.y;
    const int w0  = blockIdx.x * KQ_W;

    for (int idx = tid; idx < 128 * 160; idx += 256) {
        int oc = idx / 160, r = idx - oc * 160;
        wq_s[oc * 161 + r] = wQ[idx];
    }
    const int tstart = (w0 - 2) * P_;
    for (int idx = tid; idx < 128 * 64; idx += 256) {
        int ic = idx >> 6, j = idx & 63;
        int t  = tstart + j;
        float v = 0.f;
        if (t >= 0 && t < T_) v = cond[((size_t)b * C_ + ic) * T_ + t];
        cs[idx] = v;
    }
    __syncthreads();

    const int oc = tid & 127;
    const int p0 = (tid >> 7) * 4;
    const float bq = __ldg(&bQ[oc]);
    float4 acc[KQ_W];
    #pragma unroll
    for (int wl = 0; wl < KQ_W; wl++) acc[wl] = make_float4(bq, bq, bq, bq);

    const float* wrow  = wq_s + oc * 161;
    const float* cbase = cs + (oc >> 5) * 32 * 64 + p0;   // group = oc/32

    #pragma unroll 2
    for (int icl = 0; icl < 32; icl++) {
        const float* crow = cbase + icl * 64;
        const float* wr   = wrow + icl * 5;
        #pragma unroll
        for (int kh = 0; kh < 5; kh++) {
            float wv = wr[kh];
            #pragma unroll
            for (int wl = 0; wl < KQ_W; wl++) {
                float4 cv = *(const float4*)(crow + (wl + kh) * 8);
                fma4(acc[wl], wv, cv);
            }
        }
    }

    const int lane = tid & 31, wrp = tid >> 5;
    #pragma unroll
    for (int wl = 0; wl < KQ_W; wl++) {
        float4 a = acc[wl];
        float mx = fmaxf(fmaxf(a.x, a.y), fmaxf(a.z, a.w));
        #pragma unroll
        for (int off = 16; off; off >>= 1)
            mx = fmaxf(mx, __shfl_xor_sync(0xffffffffu, mx, off));
        if (lane == 0) red[wrp] = mx;
        __syncthreads();
        mx = red[0];
        #pragma unroll
        for (int k = 1; k < 8; k++) mx = fmaxf(mx, red[k]);

        float4 e;
        e.x = __expf(a.x - mx); e.y = __expf(a.y - mx);
        e.z = __expf(a.z - mx); e.w = __expf(a.w - mx);
        float s = e.x + e.y + e.z + e.w;
        #pragma unroll
        for (int off = 16; off; off >>= 1)
            s += __shfl_xor_sync(0xffffffffu, s, off);
        __syncthreads();                 // red reuse hazard
        if (lane == 0) red[wrp] = s;
        __syncthreads();
        float tot = red[0];
        #pragma unroll
        for (int k = 1; k < 8; k++) tot += red[k];
        float rinv = 1.f / tot;
        e.x *= rinv; e.y *= rinv; e.z *= rinv; e.w *= rinv;

        *(float4*)&g_q[((size_t)b * W_ + (w0 + wl)) * CP_ + oc * 8 + p0] = e;
        __syncthreads();                 // red reuse for next wl
    }
}

// =====================================================================
// Kernel B: KV grouped conv (256 out ch, groups=4 -> 64 oc/group) + mask on K
// block = (b, 4 w), 256 threads; thread: oc = tid, all 8 p
// =====================================================================
__global__ __launch_bounds__(256, 1)
void kKV(const float* __restrict__ x, const float* __restrict__ mask,
         const float* __restrict__ wKV, const float* __restrict__ bKV)
{
    extern __shared__ float sm[];
    float* wk_s = sm;                 // 256 * 161
    float* xs   = sm + 256 * 161;     // 128 * 64

    const int tid = threadIdx.x;
    const int b   = blockIdx.y;
    const int w0  = blockIdx.x * KQ_W;

    for (int idx = tid; idx < 256 * 160; idx += 256) {
        int oc = idx / 160, r = idx - oc * 160;
        wk_s[oc * 161 + r] = wKV[idx];
    }
    const int tstart = (w0 - 2) * P_;
    for (int idx = tid; idx < 128 * 64; idx += 256) {
        int ic = idx >> 6, j = idx & 63;
        int t  = tstart + j;
        float v = 0.f;
        if (t >= 0 && t < T_) v = x[((size_t)b * C_ + ic) * T_ + t];
        xs[idx] = v;
    }
    __syncthreads();

    const int oc = tid;
    const float bk = __ldg(&bKV[oc]);
    float4 acc[KQ_W][2];
    #pragma unroll
    for (int wl = 0; wl < KQ_W; wl++) {
        acc[wl][0] = make_float4(bk, bk, bk, bk);
        acc[wl][1] = make_float4(bk, bk, bk, bk);
    }

    const float* wrow  = wk_s + oc * 161;
    const float* cbase = xs + (oc >> 6) * 32 * 64;   // group = oc/64

    #pragma unroll 2
    for (int icl = 0; icl < 32; icl++) {
        const float* crow = cbase + icl * 64;
        const float* wr   = wrow + icl * 5;
        #pragma unroll
        for (int kh = 0; kh < 5; kh++) {
            float wv = wr[kh];
            #pragma unroll
            for (int wl = 0; wl < KQ_W; wl++) {
                float4 c0 = *(const float4*)(crow + (wl + kh) * 8);
                float4 c1 = *(const float4*)(crow + (wl + kh) * 8 + 4);
                fma4(acc[wl][0], wv, c0);
                fma4(acc[wl][1], wv, c1);
            }
        }
    }

    #pragma unroll
    for (int wl = 0; wl < KQ_W; wl++) {
        int w = w0 + wl;
        if (oc < 128) {
            const float4* mp =
                (const float4*)&mask[(((size_t)b * 128 + oc) * W_ + w) * 8];
            float4 m0 = mp[0], m1 = mp[1];
            acc[wl][0].x += m0.x; acc[wl][0].y += m0.y;
            acc[wl][0].z += m0.z; acc[wl][0].w += m0.w;
            acc[wl][1].x += m1.x; acc[wl][1].y += m1.y;
            acc[wl][1].z += m1.z; acc[wl][1].w += m1.w;
            float* dst = &g_k[((size_t)b * W_ + w) * CP_ + oc * 8];
            ((float4*)dst)[0] = acc[wl][0];
            ((float4*)dst)[1] = acc[wl][1];
        } else {
            float* dst = &g_v[((size_t)b * W_ + w) * CP_ + (oc - 128) * 8];
            ((float4*)dst)[0] = acc[wl][0];
            ((float4*)dst)[1] = acc[wl][1];
        }
    }
}

// =====================================================================
// Kernel C: per-column (over w) max and 1/sum(exp) of g_k
// grid (8 i-chunks, B); 256 threads: i = bx*128 + (tid&127), half = tid>>7
// =====================================================================
__global__ __launch_bounds__(256, 4)
void kStat()
{
    __shared__ float sm[256];
    const int tid  = threadIdx.x;
    const int b    = blockIdx.y;
    const int i    = blockIdx.x * 128 + (tid & 127);
    const int half = tid >> 7;
    const float* col = &g_k[(size_t)b * W_ * CP_ + i];

    float mx = -3.4e38f;
    #pragma unroll 4
    for (int w = half; w < W_; w += 2)
        mx = fmaxf(mx, col[(size_t)w * CP_]);
    sm[tid] = mx;
    __syncthreads();
    mx = fmaxf(sm[tid & 127], sm[(tid & 127) + 128]);
    __syncthreads();

    float s = 0.f;
    #pragma unroll 4
    for (int w = half; w < W_; w += 2)
        s += __expf(col[(size_t)w * CP_] - mx);
    sm[tid] = s;
    __syncthreads();
    if (half == 0) {
        float tot = sm[tid] + sm[tid + 128];
        g_m [b * CP_ + i] = mx;
        g_rs[b * CP_ + i] = 1.f / tot;
    }
}

// =====================================================================
// Kernel D: kv[b][i][j] = sum_w softmax_w(k)[w][i] * v[w][j]
// 128x128 tile, Kc=8, 256 thr, 8x8 micro; exp/rs fused at A-tile load.
// =====================================================================
__global__ __launch_bounds__(256, 2)
void kGemmKV()
{
    __shared__ __align__(16) float As[8 * 128];
    __shared__ __align__(16) float Bs[8 * 128];
    __shared__ float ms[128], rs[128];

    const int tid = threadIdx.x;
    const int b  = blockIdx.z;
    const int m0 = blockIdx.y * 128, n0 = blockIdx.x * 128;
    const int tx = tid & 15, ty = tid >> 4;

    if (tid < 128) {
        ms[tid] = g_m [b * CP_ + m0 + tid];
        rs[tid] = g_rs[b * CP_ + m0 + tid];
    }

    float4 c00[4], c01[4], c10[4], c11[4];
    #pragma unroll
    for (int r = 0; r < 4; r++) {
        c00[r] = make_float4(0, 0, 0, 0); c01[r] = c00[r];
        c10[r] = c00[r];                  c11[r] = c00[r];
    }

    const float* Ag = &g_k[(size_t)b * W_ * CP_ + m0];
    const float* Bg = &g_v[(size_t)b * W_ * CP_ + n0];
    const int lr = tid >> 5, lc4 = (tid & 31) * 4;
    __syncthreads();
    const float4 mm = *(const float4*)&ms[lc4];
    const float4 rr = *(const float4*)&rs[lc4];

    for (int kc = 0; kc < W_; kc += 8) {
        float4 av = *(const float4*)(Ag + (size_t)(kc + lr) * CP_ + lc4);
        av.x = __expf(av.x - mm.x) * rr.x;
        av.y = __expf(av.y - mm.y) * rr.y;
        av.z = __expf(av.z - mm.z) * rr.z;
        av.w = __expf(av.w - mm.w) * rr.w;
        float4 bv = *(const float4*)(Bg + (size_t)(kc + lr) * CP_ + lc4);
        *(float4*)&As[lr * 128 + lc4] = av;
        *(float4*)&Bs[lr * 128 + lc4] = bv;
        __syncthreads();
        #pragma unroll
        for (int kk = 0; kk < 8; kk++) {
            float4 a0 = *(const float4*)&As[kk * 128 + ty * 4];
            float4 a1 = *(const float4*)&As[kk * 128 + 64 + ty * 4];
            float4 b0 = *(const float4*)&Bs[kk * 128 + tx * 4];
            float4 b1 = *(const float4*)&Bs[kk * 128 + 64 + tx * 4];
            fma4(c00[0], a0.x, b0); fma4(c00[1], a0.y, b0);
            fma4(c00[2], a0.z, b0); fma4(c00[3], a0.w, b0);
            fma4(c01[0], a0.x, b1); fma4(c01[1], a0.y, b1);
            fma4(c01[2], a0.z, b1); fma4(c01[3], a0.w, b1);
            fma4(c10[0], a1.x, b0); fma4(c10[1], a1.y, b0);
            fma4(c10[2], a1.z, b0); fma4(c10[3], a1.w, b0);
            fma4(c11[0], a1.x, b1); fma4(c11[1], a1.y, b1);
            fma4(c11[2], a1.z, b1); fma4(c11[3], a1.w, b1);
        }
        __syncthreads();
    }

    float* Cg = &g_kv[((size_t)b * CP_ + m0) * CP_ + n0];
    #pragma unroll
    for (int r = 0; r < 4; r++) {
        *(float4*)(Cg + (size_t)(ty * 4 + r) * CP_ + tx * 4)           = c00[r];
        *(float4*)(Cg + (size_t)(ty * 4 + r) * CP_ + 64 + tx * 4)      = c01[r];
        *(float4*)(Cg + (size_t)(64 + ty * 4 + r) * CP_ + tx * 4)      = c10[r];
        *(float4*)(Cg + (size_t)(64 + ty * 4 + r) * CP_ + 64 + tx * 4) = c11[r];
    }
}

// =====================================================================
// Kernel E: attn[w][i] = q[w][:] @ kv[:][i]; epilogue writes [b][m][t] layout
// =====================================================================
__global__ __launch_bounds__(256, 2)
void kGemmAttn()
{
    __shared__ __align__(16) float As[8 * 128];
    __shared__ __align__(16) float Bs[8 * 128];

    const int tid = threadIdx.x;
    const int b  = blockIdx.z;
    const int m0 = blockIdx.y * 128, n0 = blockIdx.x * 128;
    const int tx = tid & 15, ty = tid >> 4;

    float4 c00[4], c01[4], c10[4], c11[4];
    #pragma unroll
    for (int r = 0; r < 4; r++) {
        c00[r] = make_float4(0, 0, 0, 0); c01[r] = c00[r];
        c10[r] = c00[r];                  c11[r] = c00[r];
    }

    const float* Ag = &g_q [((size_t)b * W_ + m0) * CP_];
    const float* Bg = &g_kv[((size_t)b * CP_) * CP_ + n0];
    const int ar = tid >> 1, akq = (tid & 1) * 4;   // A: [m][k] -> transpose into smem
    const int br = tid >> 5, bc4 = (tid & 31) * 4;

    for (int kc = 0; kc < CP_; kc += 8) {
        float4 av = *(const float4*)(Ag + (size_t)ar * CP_ + kc + akq);
        float4 bv = *(const float4*)(Bg + (size_t)(kc + br) * CP_ + bc4);
        As[(akq + 0) * 128 + ar] = av.x;
        As[(akq + 1) * 128 + ar] = av.y;
        As[(akq + 2) * 128 + ar] = av.z;
        As[(akq + 3) * 128 + ar] = av.w;
        *(float4*)&Bs[br * 128 + bc4] = bv;
        __syncthreads();
        #pragma unroll
        for (int kk = 0; kk < 8; kk++) {
            float4 a0 = *(const float4*)&As[kk * 128 + ty * 4];
            float4 a1 = *(const float4*)&As[kk * 128 + 64 + ty * 4];
            float4 b0 = *(const float4*)&Bs[kk * 128 + tx * 4];
            float4 b1 = *(const float4*)&Bs[kk * 128 + 64 + tx * 4];
            fma4(c00[0], a0.x, b0); fma4(c00[1], a0.y, b0);
            fma4(c00[2], a0.z, b0); fma4(c00[3], a0.w, b0);
            fma4(c01[0], a0.x, b1); fma4(c01[1], a0.y, b1);
            fma4(c01[2], a0.z, b1); fma4(c01[3], a0.w, b1);
            fma4(c10[0], a1.x, b0); fma4(c10[1], a1.y, b0);
            fma4(c10[2], a1.z, b0); fma4(c10[3], a1.w, b0);
            fma4(c11[0], a1.x, b1); fma4(c11[1], a1.y, b1);
            fma4(c11[2], a1.z, b1); fma4(c11[3], a1.w, b1);
        }
        __syncthreads();
    }

    // scatter to [b][oc][w*8+p]; nb multiple of 4 -> single oc per float4
    #pragma unroll
    for (int r = 0; r < 4; r++) {
        int w0r = m0 + ty * 4 + r;
        int w1r = m0 + 64 + ty * 4 + r;
        int nbA = n0 + tx * 4;
        int nbB = n0 + 64 + tx * 4;
        int ocA = nbA >> 3, pA = nbA & 7;
        int ocB = nbB >> 3, pB = nbB & 7;
        *(float4*)&g_at[((size_t)b * 128 + ocA) * T_ + (size_t)w0r * 8 + pA] = c00[r];
        *(float4*)&g_at[((size_t)b * 128 + ocB) * T_ + (size_t)w0r * 8 + pB] = c01[r];
        *(float4*)&g_at[((size_t)b * 128 + ocA) * T_ + (size_t)w1r * 8 + pA] = c10[r];
        *(float4*)&g_at[((size_t)b * 128 + ocB) * T_ + (size_t)w1r * 8 + pB] = c11[r];
    }
}

// =====================================================================
// Kernel F: conv1d as GEMM: out[b][c][t] = bOut[c] + sum_{m,kt} at[b][m][t+kt-1]*wOut[c][m*3+kt]
// M=128(c) x N=16384(t) x K=384; grid (128 t-tiles, B)
// =====================================================================
__global__ __launch_bounds__(256, 2)
void kConvOut(const float* __restrict__ wOut, const float* __restrict__ bOut,
              float* __restrict__ out)
{
    __shared__ __align__(16) float As[8 * 128];
    __shared__ __align__(16) float Bs[8 * 128];

    const int tid = threadIdx.x;
    const int b  = blockIdx.y;
    const int t0 = blockIdx.x * 128;
    const int tx = tid & 15, ty = tid >> 4;

    float4 c00[4], c01[4], c10[4], c11[4];
    #pragma unroll
    for (int r = 0; r < 4; r++) {
        c00[r] = make_float4(0, 0, 0, 0); c01[r] = c00[r];
        c10[r] = c00[r];                  c11[r] = c00[r];
    }

    const float* Ab = &g_at[(size_t)b * 128 * T_];
    const int ar = tid >> 1, akq = (tid & 1) * 4;
    const int br = tid >> 5, bc4 = (tid & 31) * 4;

    for (int kc = 0; kc < 384; kc += 8) {
        float4 av = *(const float4*)(wOut + (size_t)ar * 384 + kc + akq);
        As[(akq + 0) * 128 + ar] = av.x;
        As[(akq + 1) * 128 + ar] = av.y;
        As[(akq + 2) * 128 + ar] = av.z;
        As[(akq + 3) * 128 + ar] = av.w;

        int kg = kc + br;
        int mI = kg / 3, kt = kg - mI * 3;
        const float* rowp = Ab + (size_t)mI * T_;
        #pragma unroll
        for (int cc = 0; cc < 4; cc++) {
            int t = t0 + bc4 + cc + kt - 1;
            Bs[br * 128 + bc4 + cc] = (t >= 0 && t < T_) ? rowp[t] : 0.f;
        }
        __syncthreads();
        #pragma unroll
        for (int kk = 0; kk < 8; kk++) {
            float4 a0 = *(const float4*)&As[kk * 128 + ty * 4];
            float4 a1 = *(const float4*)&As[kk * 128 + 64 + ty * 4];
            float4 b0 = *(const float4*)&Bs[kk * 128 + tx * 4];
            float4 b1 = *(const float4*)&Bs[kk * 128 + 64 + tx * 4];
            fma4(c00[0], a0.x, b0); fma4(c00[1], a0.y, b0);
            fma4(c00[2], a0.z, b0); fma4(c00[3], a0.w, b0);
            fma4(c01[0], a0.x, b1); fma4(c01[1], a0.y, b1);
            fma4(c01[2], a0.z, b1); fma4(c01[3], a0.w, b1);
            fma4(c10[0], a1.x, b0); fma4(c10[1], a1.y, b0);
            fma4(c10[2], a1.z, b0); fma4(c10[3], a1.w, b0);
            fma4(c11[0], a1.x, b1); fma4(c11[1], a1.y, b1);
            fma4(c11[2], a1.z, b1); fma4(c11[3], a1.w, b1);
        }
        __syncthreads();
    }

    #pragma unroll
    for (int r = 0; r < 4; r++) {
        int mA = ty * 4 + r;
        int mB = 64 + ty * 4 + r;
        float biA = __ldg(&bOut[mA]);
        float biB = __ldg(&bOut[mB]);
        float4 o;
        float* rowA = out + ((size_t)b * 128 + mA) * T_ + t0;
        float* rowB = out + ((size_t)b * 128 + mB) * T_ + t0;
        o = c00[r]; o.x += biA; o.y += biA; o.z += biA; o.w += biA;
        *(float4*)(rowA + tx * 4) = o;
        o = c01[r]; o.x += biA; o.y += biA; o.z += biA; o.w += biA;
        *(float4*)(rowA + 64 + tx * 4) = o;
        o = c10[r]; o.x += biB; o.y += biB; o.z += biB; o.w += biB;
        *(float4*)(rowB + tx * 4) = o;
        o = c11[r]; o.x += biB; o.y += biB; o.z += biB; o.w += biB;
        *(float4*)(rowB + 64 + tx * 4) = o;
    }
}

// =====================================================================
// launcher
// =====================================================================
extern "C" void kernel_launch(void* const* d_in, const int* in_sizes, int n_in,
                              void* d_out, int out_size)
{
    (void)in_sizes; (void)n_in; (void)out_size;
    const float* x    = (const float*)d_in[0];
    const float* cond = (const float*)d_in[1];
    const float* mask = (const float*)d_in[2];
    const float* wQ   = (const float*)d_in[3];
    const float* bQ   = (const float*)d_in[4];
    const float* wKV  = (const float*)d_in[5];
    const float* bKV  = (const float*)d_in[6];
    const float* wOut = (const float*)d_in[7];
    const float* bOut = (const float*)d_in[8];
    float* out = (float*)d_out;

    const size_t smA = (size_t)(128 * 161 + 128 * 64 + 64) * sizeof(float);   // ~115 KB
    const size_t smB = (size_t)(256 * 161 + 128 * 64) * sizeof(float);        // ~198 KB
    cudaFuncSetAttribute(kQ,  cudaFuncAttributeMaxDynamicSharedMemorySize, (int)smA);
    cudaFuncSetAttribute(kKV, cudaFuncAttributeMaxDynamicSharedMemorySize, (int)smB);

    kQ  <<<dim3(W_ / KQ_W, B_), 256, smA>>>(cond, wQ, bQ);
    kKV <<<dim3(W_ / KQ_W, B_), 256, smB>>>(x, mask, wKV, bKV);
    kStat<<<dim3(CP_ / 128, B_), 256>>>();
    kGemmKV  <<<dim3(CP_ / 128, CP_ / 128, B_), 256>>>();
    kGemmAttn<<<dim3(CP_ / 128, W_  / 128, B_), 256>>>();
    kConvOut <<<dim3(T_ / 128, B_), 256>>>(wOut, bOut, out);
}

// round 3
// speedup vs baseline: 1.5550x; 1.5550x over previous
#include <cuda_runtime.h>
#include <cstdint>

// ---------------- problem constants ----------------
#define B_    16
#define C_    128
#define T_    16384
#define W_    2048      // wordnum = T/patch
#define P_    8
#define MIDC_ 128
#define CP_   1024      // MIDC * P

// ---------------- scratch (device globals; allocation-free rule) ----------------
__device__ float g_q [(size_t)B_ * W_ * CP_];   // tf32 softmaxed Q [b][w][i]
__device__ float g_k [(size_t)B_ * W_ * CP_];   // raw K + mask     [b][w][i]
__device__ float g_v [(size_t)B_ * W_ * CP_];   // raw V            [b][w][i]
__device__ float g_kt[(size_t)B_ * CP_ * W_];   // tf32 softmax(K)^T [b][i][w]
__device__ float g_vt[(size_t)B_ * CP_ * W_];   // tf32 V^T          [b][i][w]
__device__ float g_kv[(size_t)B_ * CP_ * CP_];  // tf32 kv_mat^T     [b][i][j]
__device__ float g_at[(size_t)B_ * MIDC_ * T_]; // attn out fp32     [b][m][t]
__device__ float g_m [B_ * CP_];                // column max of K
__device__ float g_rs[B_ * CP_];                // 1 / column sum(exp)

// ---------------- helpers ----------------
__device__ __forceinline__ void fma4(float4 &c, float a, const float4 &b) {
    c.x = fmaf(a, b.x, c.x);
    c.y = fmaf(a, b.y, c.y);
    c.z = fmaf(a, b.z, c.z);
    c.w = fmaf(a, b.w, c.w);
}

__device__ __forceinline__ uint32_t smem_u32(const void* p) {
    uint32_t a;
    asm("{ .reg .u64 t; cvta.to.shared.u64 t, %1; cvt.u32.u64 %0, t; }"
        : "=r"(a) : "l"(p));
    return a;
}

__device__ __forceinline__ float to_tf32(float x) {
    uint32_t u;
    asm("cvt.rna.tf32.f32 %0, %1;" : "=r"(u) : "f"(x));
    return __uint_as_float(u);
}

#define LDSM4(r, addr)                                                        \
    asm volatile("ldmatrix.sync.aligned.m8n8.x4.shared.b16 {%0,%1,%2,%3}, [%4];" \
        : "=r"((r)[0]), "=r"((r)[1]), "=r"((r)[2]), "=r"((r)[3]) : "r"(addr))

__device__ __forceinline__ void mma_tf32(float* c, const uint32_t* a,
                                         uint32_t b0, uint32_t b1) {
    asm volatile(
        "mma.sync.aligned.m16n8k8.row.col.f32.tf32.tf32.f32 "
        "{%0,%1,%2,%3}, {%4,%5,%6,%7}, {%8,%9}, {%0,%1,%2,%3};"
        : "+f"(c[0]), "+f"(c[1]), "+f"(c[2]), "+f"(c[3])
        : "r"(a[0]), "r"(a[1]), "r"(a[2]), "r"(a[3]), "r"(b0), "r"(b1));
}

// =====================================================================
// Kernel A: Q grouped conv (5 taps, groups=4) + fused softmax over i (tf32 out)
// =====================================================================
#define KQ_W  4
__global__ __launch_bounds__(256, 1)
void kQ(const float* __restrict__ cond,
        const float* __restrict__ wQ, const float* __restrict__ bQ)
{
    extern __shared__ float sm[];
    float* wq_s = sm;                 // 128 * 161
    float* cs   = sm + 128 * 161;     // 128 ic * 64 t
    float* red  = cs + 128 * 64;      // 8 warp partials

    const int tid = threadIdx.x;
    const int b   = blockIdx.y;
    const int w0  = blockIdx.x * KQ_W;

    for (int idx = tid; idx < 128 * 160; idx += 256) {
        int oc = idx / 160, r = idx - oc * 160;
        wq_s[oc * 161 + r] = wQ[idx];
    }
    const int tstart = (w0 - 2) * P_;
    for (int idx = tid; idx < 128 * 64; idx += 256) {
        int ic = idx >> 6, j = idx & 63;
        int t  = tstart + j;
        float v = 0.f;
        if (t >= 0 && t < T_) v = cond[((size_t)b * C_ + ic) * T_ + t];
        cs[idx] = v;
    }
    __syncthreads();

    const int oc = tid & 127;
    const int p0 = (tid >> 7) * 4;
    const float bq = __ldg(&bQ[oc]);
    float4 acc[KQ_W];
    #pragma unroll
    for (int wl = 0; wl < KQ_W; wl++) acc[wl] = make_float4(bq, bq, bq, bq);

    const float* wrow  = wq_s + oc * 161;
    const float* cbase = cs + (oc >> 5) * 32 * 64 + p0;

    #pragma unroll 2
    for (int icl = 0; icl < 32; icl++) {
        const float* crow = cbase + icl * 64;
        const float* wr   = wrow + icl * 5;
        #pragma unroll
        for (int kh = 0; kh < 5; kh++) {
            float wv = wr[kh];
            #pragma unroll
            for (int wl = 0; wl < KQ_W; wl++) {
                float4 cv = *(const float4*)(crow + (wl + kh) * 8);
                fma4(acc[wl], wv, cv);
            }
        }
    }

    const int lane = tid & 31, wrp = tid >> 5;
    #pragma unroll
    for (int wl = 0; wl < KQ_W; wl++) {
        float4 a = acc[wl];
        float mx = fmaxf(fmaxf(a.x, a.y), fmaxf(a.z, a.w));
        #pragma unroll
        for (int off = 16; off; off >>= 1)
            mx = fmaxf(mx, __shfl_xor_sync(0xffffffffu, mx, off));
        if (lane == 0) red[wrp] = mx;
        __syncthreads();
        mx = red[0];
        #pragma unroll
        for (int k = 1; k < 8; k++) mx = fmaxf(mx, red[k]);

        float4 e;
        e.x = __expf(a.x - mx); e.y = __expf(a.y - mx);
        e.z = __expf(a.z - mx); e.w = __expf(a.w - mx);
        float s = e.x + e.y + e.z + e.w;
        #pragma unroll
        for (int off = 16; off; off >>= 1)
            s += __shfl_xor_sync(0xffffffffu, s, off);
        __syncthreads();
        if (lane == 0) red[wrp] = s;
        __syncthreads();
        float tot = red[0];
        #pragma unroll
        for (int k = 1; k < 8; k++) tot += red[k];
        float rinv = 1.f / tot;
        float4 o;
        o.x = to_tf32(e.x * rinv); o.y = to_tf32(e.y * rinv);
        o.z = to_tf32(e.z * rinv); o.w = to_tf32(e.w * rinv);

        *(float4*)&g_q[((size_t)b * W_ + (w0 + wl)) * CP_ + oc * 8 + p0] = o;
        __syncthreads();
    }
}

// =====================================================================
// Kernel B: KV grouped conv (256 out ch, groups=4) + mask on K
// =====================================================================
__global__ __launch_bounds__(256, 1)
void kKV(const float* __restrict__ x, const float* __restrict__ mask,
         const float* __restrict__ wKV, const float* __restrict__ bKV)
{
    extern __shared__ float sm[];
    float* wk_s = sm;                 // 256 * 161
    float* xs   = sm + 256 * 161;     // 128 * 64

    const int tid = threadIdx.x;
    const int b   = blockIdx.y;
    const int w0  = blockIdx.x * KQ_W;

    for (int idx = tid; idx < 256 * 160; idx += 256) {
        int oc = idx / 160, r = idx - oc * 160;
        wk_s[oc * 161 + r] = wKV[idx];
    }
    const int tstart = (w0 - 2) * P_;
    for (int idx = tid; idx < 128 * 64; idx += 256) {
        int ic = idx >> 6, j = idx & 63;
        int t  = tstart + j;
        float v = 0.f;
        if (t >= 0 && t < T_) v = x[((size_t)b * C_ + ic) * T_ + t];
        xs[idx] = v;
    }
    __syncthreads();

    const int oc = tid;
    const float bk = __ldg(&bKV[oc]);
    float4 acc[KQ_W][2];
    #pragma unroll
    for (int wl = 0; wl < KQ_W; wl++) {
        acc[wl][0] = make_float4(bk, bk, bk, bk);
        acc[wl][1] = make_float4(bk, bk, bk, bk);
    }

    const float* wrow  = wk_s + oc * 161;
    const float* cbase = xs + (oc >> 6) * 32 * 64;

    #pragma unroll 2
    for (int icl = 0; icl < 32; icl++) {
        const float* crow = cbase + icl * 64;
        const float* wr   = wrow + icl * 5;
        #pragma unroll
        for (int kh = 0; kh < 5; kh++) {
            float wv = wr[kh];
            #pragma unroll
            for (int wl = 0; wl < KQ_W; wl++) {
                float4 c0 = *(const float4*)(crow + (wl + kh) * 8);
                float4 c1 = *(const float4*)(crow + (wl + kh) * 8 + 4);
                fma4(acc[wl][0], wv, c0);
                fma4(acc[wl][1], wv, c1);
            }
        }
    }

    #pragma unroll
    for (int wl = 0; wl < KQ_W; wl++) {
        int w = w0 + wl;
        if (oc < 128) {
            const float4* mp =
                (const float4*)&mask[(((size_t)b * 128 + oc) * W_ + w) * 8];
            float4 m0 = mp[0], m1 = mp[1];
            acc[wl][0].x += m0.x; acc[wl][0].y += m0.y;
            acc[wl][0].z += m0.z; acc[wl][0].w += m0.w;
            acc[wl][1].x += m1.x; acc[wl][1].y += m1.y;
            acc[wl][1].z += m1.z; acc[wl][1].w += m1.w;
            float* dst = &g_k[((size_t)b * W_ + w) * CP_ + oc * 8];
            ((float4*)dst)[0] = acc[wl][0];
            ((float4*)dst)[1] = acc[wl][1];
        } else {
            float* dst = &g_v[((size_t)b * W_ + w) * CP_ + (oc - 128) * 8];
            ((float4*)dst)[0] = acc[wl][0];
            ((float4*)dst)[1] = acc[wl][1];
        }
    }
}

// =====================================================================
// Kernel C: per-column (over w) max and 1/sum(exp) of g_k
// =====================================================================
__global__ __launch_bounds__(256, 4)
void kStat()
{
    __shared__ float sm[256];
    const int tid  = threadIdx.x;
    const int b    = blockIdx.y;
    const int i    = blockIdx.x * 128 + (tid & 127);
    const int half = tid >> 7;
    const float* col = &g_k[(size_t)b * W_ * CP_ + i];

    float mx = -3.4e38f;
    #pragma unroll 4
    for (int w = half; w < W_; w += 2)
        mx = fmaxf(mx, col[(size_t)w * CP_]);
    sm[tid] = mx;
    __syncthreads();
    mx = fmaxf(sm[tid & 127], sm[(tid & 127) + 128]);
    __syncthreads();

    float s = 0.f;
    #pragma unroll 4
    for (int w = half; w < W_; w += 2)
        s += __expf(col[(size_t)w * CP_] - mx);
    sm[tid] = s;
    __syncthreads();
    if (half == 0) {
        float tot = sm[tid] + sm[tid + 128];
        g_m [b * CP_ + i] = mx;
        g_rs[b * CP_ + i] = 1.f / tot;
    }
}

// =====================================================================
// Kernel C2: transpose K (with fused softmax exp) and V into [i][w] tf32
// =====================================================================
__global__ __launch_bounds__(256, 4)
void kTrans()
{
    __shared__ float sk[32][33];
    __shared__ float sv[32][33];
    const int tid = threadIdx.x;
    const int tx = tid & 31, ty = tid >> 5;
    const int b  = blockIdx.z;
    const int w0 = blockIdx.x * 32;
    const int i0 = blockIdx.y * 32;

    #pragma unroll
    for (int r = 0; r < 4; r++) {
        int w = w0 + ty + r * 8;
        size_t src = ((size_t)b * W_ + w) * CP_ + i0 + tx;
        sk[ty + r * 8][tx] = g_k[src];
        sv[ty + r * 8][tx] = g_v[src];
    }
    __syncthreads();

    #pragma unroll
    for (int r = 0; r < 4; r++) {
        int i = i0 + ty + r * 8;
        float mv = g_m [b * CP_ + i];
        float rv = g_rs[b * CP_ + i];
        size_t dst = ((size_t)b * CP_ + i) * W_ + w0 + tx;
        g_kt[dst] = to_tf32(__expf(sk[tx][ty + r * 8] - mv) * rv);
        g_vt[dst] = to_tf32(sv[tx][ty + r * 8]);
    }
}

// =====================================================================
// Kernel D/E: tf32 mma.sync GEMM, 128x128 tile, BK=16, 4-stage cp.async.
//   EPI==0: D1[i][j] = sum_w vt[i][w]*kt[j][w]  -> g_kv (tf32, = kv_mat^T)
//   EPI==1: D2[w][i] = sum_j  q[w][j]*kv[i][j]  -> g_at scatter (fp32)
// 8 warps 2(m)x4(n); warp tile 64x32; fragments via ldmatrix.x4.
// =====================================================================
#define BKPAD   20
#define STG_SZ  (2 * 128 * BKPAD)   // floats per stage (A + B)

template<int KTOT, int MTOT, int EPI>
__global__ __launch_bounds__(256, 2)
void kGemmMMA()
{
    extern __shared__ float smemf[];
    const int tid  = threadIdx.x;
    const int lane = tid & 31, wid = tid >> 5;
    const int b  = blockIdx.z;
    const int n0 = blockIdx.x * 128;
    const int m0 = blockIdx.y * 128;

    const float* A  = (EPI == 0) ? g_vt : g_q;
    const float* Bp = (EPI == 0) ? g_kt : g_kv;

    const float* Ag = A  + (size_t)b * MTOT * KTOT + (size_t)m0 * KTOT;
    const float* Bg = Bp + (size_t)b * 1024 * KTOT + (size_t)n0 * KTOT;

    const uint32_t smem0 = smem_u32(smemf);
    const int NT = KTOT / 16;

    const int lr = tid >> 2, lc = (tid & 3) * 4;   // loader: row, float-col

    // ---- prefetch stages 0..2 ----
    #pragma unroll
    for (int s = 0; s < 3; s++) {
        uint32_t sb = smem0 + s * STG_SZ * 4;
        const float* Agt = Ag + s * 16;
        const float* Bgt = Bg + s * 16;
        #pragma unroll
        for (int h = 0; h < 2; h++) {
            int r = lr + h * 64;
            uint32_t da = sb + (r * BKPAD + lc) * 4;
            asm volatile("cp.async.cg.shared.global [%0], [%1], 16;"
                         :: "r"(da), "l"(Agt + (size_t)r * KTOT + lc));
            uint32_t db = sb + (128 * BKPAD + r * BKPAD + lc) * 4;
            asm volatile("cp.async.cg.shared.global [%0], [%1], 16;"
                         :: "r"(db), "l"(Bgt + (size_t)r * KTOT + lc));
        }
        asm volatile("cp.async.commit_group;");
    }

    const int m_warp = (wid & 1) * 64;
    const int n_warp = (wid >> 1) * 32;

    float acc[4][4][4];
    #pragma unroll
    for (int mi = 0; mi < 4; mi++)
        #pragma unroll
        for (int nb = 0; nb < 4; nb++)
            #pragma unroll
            for (int e = 0; e < 4; e++) acc[mi][nb][e] = 0.f;

    // ldmatrix lane address components
    const int a_row  = (lane < 16) ? lane : (lane - 16);
    const int a_koff = (lane < 16) ? 0 : 4;
    const int b_noff = (lane & 7) + ((lane >> 4) << 3);
    const int b_koff = ((lane >> 3) & 1) * 4;

    for (int t = 0; t < NT; t++) {
        asm volatile("cp.async.wait_group 2;");
        __syncthreads();

        // issue loads for stage t+3 (overwrites buffer read at iter t-1)
        if (t + 3 < NT) {
            uint32_t sb = smem0 + ((t + 3) & 3) * STG_SZ * 4;
            const float* Agt = Ag + (t + 3) * 16;
            const float* Bgt = Bg + (t + 3) * 16;
            #pragma unroll
            for (int h = 0; h < 2; h++) {
                int r = lr + h * 64;
                uint32_t da = sb + (r * BKPAD + lc) * 4;
                asm volatile("cp.async.cg.shared.global [%0], [%1], 16;"
                             :: "r"(da), "l"(Agt + (size_t)r * KTOT + lc));
                uint32_t db = sb + (128 * BKPAD + r * BKPAD + lc) * 4;
                asm volatile("cp.async.cg.shared.global [%0], [%1], 16;"
                             :: "r"(db), "l"(Bgt + (size_t)r * KTOT + lc));
            }
        }
        asm volatile("cp.async.commit_group;");

        const uint32_t As = smem0 + (t & 3) * STG_SZ * 4;
        const uint32_t Bs = As + 128 * BKPAD * 4;

        #pragma unroll
        for (int ks = 0; ks < 2; ks++) {
            const int k0 = ks * 8;
            uint32_t ar[4][4];
            #pragma unroll
            for (int mi = 0; mi < 4; mi++) {
                uint32_t addr = As +
                    ((m_warp + mi * 16 + a_row) * BKPAD + k0 + a_koff) * 4;
                LDSM4(ar[mi], addr);
            }
            uint32_t br[2][4];
            #pragma unroll
            for (int nb2 = 0; nb2 < 2; nb2++) {
                uint32_t addr = Bs +
                    ((n_warp + nb2 * 16 + b_noff) * BKPAD + k0 + b_koff) * 4;
                LDSM4(br[nb2], addr);
            }
            #pragma unroll
            for (int mi = 0; mi < 4; mi++)
                #pragma unroll
                for (int nb = 0; nb < 4; nb++)
                    mma_tf32(acc[mi][nb], ar[mi],
                             br[nb >> 1][(nb & 1) * 2],
                             br[nb >> 1][(nb & 1) * 2 + 1]);
        }
    }

    // ---- epilogue ----
    const int rg = lane >> 2;
    const int cg = (lane & 3) * 2;
    #pragma unroll
    for (int mi = 0; mi < 4; mi++) {
        const int row = m0 + m_warp + mi * 16 + rg;
        #pragma unroll
        for (int nb = 0; nb < 4; nb++) {
            const int col = n0 + n_warp + nb * 8 + cg;
            const float* c = acc[mi][nb];
            if (EPI == 0) {
                float2 lo = make_float2(to_tf32(c[0]), to_tf32(c[1]));
                float2 hi = make_float2(to_tf32(c[2]), to_tf32(c[3]));
                *(float2*)&g_kv[((size_t)b * CP_ + row)     * CP_ + col] = lo;
                *(float2*)&g_kv[((size_t)b * CP_ + row + 8) * CP_ + col] = hi;
            } else {
                const int oc = col >> 3, p = col & 7;
                float* base = &g_at[((size_t)b * MIDC_ + oc) * T_];
                *(float2*)&base[(size_t)row * 8 + p]       = make_float2(c[0], c[1]);
                *(float2*)&base[(size_t)(row + 8) * 8 + p] = make_float2(c[2], c[3]);
            }
        }
    }
}

// =====================================================================
// Kernel F: conv1d as GEMM (fp32): out[b][c][t]
// =====================================================================
__global__ __launch_bounds__(256, 2)
void kConvOut(const float* __restrict__ wOut, const float* __restrict__ bOut,
              float* __restrict__ out)
{
    __shared__ __align__(16) float As[8 * 128];
    __shared__ __align__(16) float Bs[8 * 128];

    const int tid = threadIdx.x;
    const int b  = blockIdx.y;
    const int t0 = blockIdx.x * 128;
    const int tx = tid & 15, ty = tid >> 4;

    float4 c00[4], c01[4], c10[4], c11[4];
    #pragma unroll
    for (int r = 0; r < 4; r++) {
        c00[r] = make_float4(0, 0, 0, 0); c01[r] = c00[r];
        c10[r] = c00[r];                  c11[r] = c00[r];
    }

    const float* Ab = &g_at[(size_t)b * 128 * T_];
    const int ar = tid >> 1, akq = (tid & 1) * 4;
    const int br = tid >> 5, bc4 = (tid & 31) * 4;

    for (int kc = 0; kc < 384; kc += 8) {
        float4 av = *(const float4*)(wOut + (size_t)ar * 384 + kc + akq);
        As[(akq + 0) * 128 + ar] = av.x;
        As[(akq + 1) * 128 + ar] = av.y;
        As[(akq + 2) * 128 + ar] = av.z;
        As[(akq + 3) * 128 + ar] = av.w;

        int kg = kc + br;
        int mI = kg / 3, kt = kg - mI * 3;
        const float* rowp = Ab + (size_t)mI * T_;
        #pragma unroll
        for (int cc = 0; cc < 4; cc++) {
            int t = t0 + bc4 + cc + kt - 1;
            Bs[br * 128 + bc4 + cc] = (t >= 0 && t < T_) ? rowp[t] : 0.f;
        }
        __syncthreads();
        #pragma unroll
        for (int kk = 0; kk < 8; kk++) {
            float4 a0 = *(const float4*)&As[kk * 128 + ty * 4];
            float4 a1 = *(const float4*)&As[kk * 128 + 64 + ty * 4];
            float4 b0 = *(const float4*)&Bs[kk * 128 + tx * 4];
            float4 b1 = *(const float4*)&Bs[kk * 128 + 64 + tx * 4];
            fma4(c00[0], a0.x, b0); fma4(c00[1], a0.y, b0);
            fma4(c00[2], a0.z, b0); fma4(c00[3], a0.w, b0);
            fma4(c01[0], a0.x, b1); fma4(c01[1], a0.y, b1);
            fma4(c01[2], a0.z, b1); fma4(c01[3], a0.w, b1);
            fma4(c10[0], a1.x, b0); fma4(c10[1], a1.y, b0);
            fma4(c10[2], a1.z, b0); fma4(c10[3], a1.w, b0);
            fma4(c11[0], a1.x, b1); fma4(c11[1], a1.y, b1);
            fma4(c11[2], a1.z, b1); fma4(c11[3], a1.w, b1);
        }
        __syncthreads();
    }

    #pragma unroll
    for (int r = 0; r < 4; r++) {
        int mA = ty * 4 + r;
        int mB = 64 + ty * 4 + r;
        float biA = __ldg(&bOut[mA]);
        float biB = __ldg(&bOut[mB]);
        float4 o;
        float* rowA = out + ((size_t)b * 128 + mA) * T_ + t0;
        float* rowB = out + ((size_t)b * 128 + mB) * T_ + t0;
        o = c00[r]; o.x += biA; o.y += biA; o.z += biA; o.w += biA;
        *(float4*)(rowA + tx * 4) = o;
        o = c01[r]; o.x += biA; o.y += biA; o.z += biA; o.w += biA;
        *(float4*)(rowA + 64 + tx * 4) = o;
        o = c10[r]; o.x += biB; o.y += biB; o.z += biB; o.w += biB;
        *(float4*)(rowB + tx * 4) = o;
        o = c11[r]; o.x += biB; o.y += biB; o.z += biB; o.w += biB;
        *(float4*)(rowB + 64 + tx * 4) = o;
    }
}

// =====================================================================
// launcher
// =====================================================================
extern "C" void kernel_launch(void* const* d_in, const int* in_sizes, int n_in,
                              void* d_out, int out_size)
{
    (void)in_sizes; (void)n_in; (void)out_size;
    const float* x    = (const float*)d_in[0];
    const float* cond = (const float*)d_in[1];
    const float* mask = (const float*)d_in[2];
    const float* wQ   = (const float*)d_in[3];
    const float* bQ   = (const float*)d_in[4];
    const float* wKV  = (const float*)d_in[5];
    const float* bKV  = (const float*)d_in[6];
    const float* wOut = (const float*)d_in[7];
    const float* bOut = (const float*)d_in[8];
    float* out = (float*)d_out;

    const size_t smA = (size_t)(128 * 161 + 128 * 64 + 64) * sizeof(float);
    const size_t smB = (size_t)(256 * 161 + 128 * 64) * sizeof(float);
    const size_t smG = (size_t)4 * STG_SZ * sizeof(float);   // 80 KB
    cudaFuncSetAttribute(kQ,  cudaFuncAttributeMaxDynamicSharedMemorySize, (int)smA);
    cudaFuncSetAttribute(kKV, cudaFuncAttributeMaxDynamicSharedMemorySize, (int)smB);
    cudaFuncSetAttribute(kGemmMMA<2048, 1024, 0>,
                         cudaFuncAttributeMaxDynamicSharedMemorySize, (int)smG);
    cudaFuncSetAttribute(kGemmMMA<1024, 2048, 1>,
                         cudaFuncAttributeMaxDynamicSharedMemorySize, (int)smG);

    kQ   <<<dim3(W_ / KQ_W, B_), 256, smA>>>(cond, wQ, bQ);
    kKV  <<<dim3(W_ / KQ_W, B_), 256, smB>>>(x, mask, wKV, bKV);
    kStat<<<dim3(CP_ / 128, B_), 256>>>();
    kTrans<<<dim3(W_ / 32, CP_ / 32, B_), 256>>>();
    // GEMM1: D1[i][j] = sum_w vt[i][w] * kt[j][w]   (M=1024, N=1024, K=2048)
    kGemmMMA<2048, 1024, 0><<<dim3(CP_ / 128, CP_ / 128, B_), 256, smG>>>();
    // GEMM2: D2[w][i] = sum_j q[w][j] * kv[i][j]    (M=2048, N=1024, K=1024)
    kGemmMMA<1024, 2048, 1><<<dim3(CP_ / 128, W_ / 128, B_), 256, smG>>>();
    kConvOut<<<dim3(T_ / 128, B_), 256>>>(wOut, bOut, out);
}

// round 4
// speedup vs baseline: 1.8525x; 1.1913x over previous
#include <cuda_runtime.h>
#include <cstdint>

// ---------------- problem constants ----------------
#define B_    16
#define C_    128
#define T_    16384
#define W_    2048      // wordnum = T/patch
#define P_    8
#define MIDC_ 128
#define CP_   1024      // MIDC * P

// ---------------- scratch (device globals; allocation-free rule) ----------------
__device__ float g_q [(size_t)B_ * W_ * CP_];   // tf32 softmaxed Q [b][w][i]
__device__ float g_k [(size_t)B_ * W_ * CP_];   // raw K + mask     [b][w][i]
__device__ float g_v [(size_t)B_ * W_ * CP_];   // raw V            [b][w][i]
__device__ float g_kt[(size_t)B_ * CP_ * W_];   // tf32 softmax(K)^T [b][i][w]
__device__ float g_vt[(size_t)B_ * CP_ * W_];   // tf32 V^T          [b][i][w]
__device__ float g_kv[(size_t)B_ * CP_ * CP_];  // tf32 kv_mat^T     [b][i][j]
__device__ float g_at[(size_t)B_ * MIDC_ * T_]; // attn out fp32     [b][m][t]
__device__ float g_m [B_ * CP_];                // column max of K
__device__ float g_rs[B_ * CP_];                // 1 / column sum(exp)

// ---------------- helpers ----------------
__device__ __forceinline__ void fma4(float4 &c, float a, const float4 &b) {
    c.x = fmaf(a, b.x, c.x);
    c.y = fmaf(a, b.y, c.y);
    c.z = fmaf(a, b.z, c.z);
    c.w = fmaf(a, b.w, c.w);
}

__device__ __forceinline__ uint32_t smem_u32(const void* p) {
    uint32_t a;
    asm("{ .reg .u64 t; cvta.to.shared.u64 t, %1; cvt.u32.u64 %0, t; }"
        : "=r"(a) : "l"(p));
    return a;
}

__device__ __forceinline__ float to_tf32(float x) {
    uint32_t u;
    asm("cvt.rna.tf32.f32 %0, %1;" : "=r"(u) : "f"(x));
    return __uint_as_float(u);
}

#define LDSM4(r, addr)                                                        \
    asm volatile("ldmatrix.sync.aligned.m8n8.x4.shared.b16 {%0,%1,%2,%3}, [%4];" \
        : "=r"((r)[0]), "=r"((r)[1]), "=r"((r)[2]), "=r"((r)[3]) : "r"(addr))

__device__ __forceinline__ void mma_tf32(float* c, const uint32_t* a,
                                         uint32_t b0, uint32_t b1) {
    asm volatile(
        "mma.sync.aligned.m16n8k8.row.col.f32.tf32.tf32.f32 "
        "{%0,%1,%2,%3}, {%4,%5,%6,%7}, {%8,%9}, {%0,%1,%2,%3};"
        : "+f"(c[0]), "+f"(c[1]), "+f"(c[2]), "+f"(c[3])
        : "r"(a[0]), "r"(a[1]), "r"(a[2]), "r"(a[3]), "r"(b0), "r"(b1));
}

// =====================================================================
// Kernel A: Q grouped conv (5 taps, groups=4) + fused softmax over i (tf32 out)
// block = (b, 8 consecutive w)
// =====================================================================
#define KQ_W  8
#define CTW   ((KQ_W + 4) * 8)    // 96 t values per ic
__global__ __launch_bounds__(256, 1)
void kQ(const float* __restrict__ cond,
        const float* __restrict__ wQ, const float* __restrict__ bQ)
{
    extern __shared__ float sm[];
    float* wq_s = sm;                   // 128 * 161
    float* cs   = sm + 128 * 161;       // 128 ic * CTW t
    float* red  = cs + 128 * CTW;       // 8 warp partials

    const int tid = threadIdx.x;
    const int b   = blockIdx.y;
    const int w0  = blockIdx.x * KQ_W;

    for (int idx = tid; idx < 128 * 160; idx += 256) {
        int oc = idx / 160, r = idx - oc * 160;
        wq_s[oc * 161 + r] = wQ[idx];
    }
    const int tstart = (w0 - 2) * P_;
    for (int idx = tid; idx < 128 * CTW; idx += 256) {
        int ic = idx / CTW, j = idx - ic * CTW;
        int t  = tstart + j;
        float v = 0.f;
        if (t >= 0 && t < T_) v = cond[((size_t)b * C_ + ic) * T_ + t];
        cs[idx] = v;
    }
    __syncthreads();

    const int oc = tid & 127;
    const int p0 = (tid >> 7) * 4;
    const float bq = __ldg(&bQ[oc]);
    float4 acc[KQ_W];
    #pragma unroll
    for (int wl = 0; wl < KQ_W; wl++) acc[wl] = make_float4(bq, bq, bq, bq);

    const float* wrow  = wq_s + oc * 161;
    const float* cbase = cs + (oc >> 5) * 32 * CTW + p0;

    #pragma unroll 2
    for (int icl = 0; icl < 32; icl++) {
        const float* crow = cbase + icl * CTW;
        const float* wr   = wrow + icl * 5;
        #pragma unroll
        for (int kh = 0; kh < 5; kh++) {
            float wv = wr[kh];
            #pragma unroll
            for (int wl = 0; wl < KQ_W; wl++) {
                float4 cv = *(const float4*)(crow + (wl + kh) * 8);
                fma4(acc[wl], wv, cv);
            }
        }
    }

    const int lane = tid & 31, wrp = tid >> 5;
    #pragma unroll
    for (int wl = 0; wl < KQ_W; wl++) {
        float4 a = acc[wl];
        float mx = fmaxf(fmaxf(a.x, a.y), fmaxf(a.z, a.w));
        #pragma unroll
        for (int off = 16; off; off >>= 1)
            mx = fmaxf(mx, __shfl_xor_sync(0xffffffffu, mx, off));
        if (lane == 0) red[wrp] = mx;
        __syncthreads();
        mx = red[0];
        #pragma unroll
        for (int k = 1; k < 8; k++) mx = fmaxf(mx, red[k]);

        float4 e;
        e.x = __expf(a.x - mx); e.y = __expf(a.y - mx);
        e.z = __expf(a.z - mx); e.w = __expf(a.w - mx);
        float s = e.x + e.y + e.z + e.w;
        #pragma unroll
        for (int off = 16; off; off >>= 1)
            s += __shfl_xor_sync(0xffffffffu, s, off);
        __syncthreads();
        if (lane == 0) red[wrp] = s;
        __syncthreads();
        float tot = red[0];
        #pragma unroll
        for (int k = 1; k < 8; k++) tot += red[k];
        float rinv = 1.f / tot;
        float4 o;
        o.x = to_tf32(e.x * rinv); o.y = to_tf32(e.y * rinv);
        o.z = to_tf32(e.z * rinv); o.w = to_tf32(e.w * rinv);

        *(float4*)&g_q[((size_t)b * W_ + (w0 + wl)) * CP_ + oc * 8 + p0] = o;
        __syncthreads();
    }
}

// =====================================================================
// Kernel B: KV grouped conv (256 out ch, groups=4) + mask on K
// =====================================================================
__global__ __launch_bounds__(256, 1)
void kKV(const float* __restrict__ x, const float* __restrict__ mask,
         const float* __restrict__ wKV, const float* __restrict__ bKV)
{
    extern __shared__ float sm[];
    float* wk_s = sm;                   // 256 * 161
    float* xs   = sm + 256 * 161;       // 128 * CTW

    const int tid = threadIdx.x;
    const int b   = blockIdx.y;
    const int w0  = blockIdx.x * KQ_W;

    for (int idx = tid; idx < 256 * 160; idx += 256) {
        int oc = idx / 160, r = idx - oc * 160;
        wk_s[oc * 161 + r] = wKV[idx];
    }
    const int tstart = (w0 - 2) * P_;
    for (int idx = tid; idx < 128 * CTW; idx += 256) {
        int ic = idx / CTW, j = idx - ic * CTW;
        int t  = tstart + j;
        float v = 0.f;
        if (t >= 0 && t < T_) v = x[((size_t)b * C_ + ic) * T_ + t];
        xs[idx] = v;
    }
    __syncthreads();

    const int oc = tid;
    const float bk = __ldg(&bKV[oc]);
    float4 acc[KQ_W][2];
    #pragma unroll
    for (int wl = 0; wl < KQ_W; wl++) {
        acc[wl][0] = make_float4(bk, bk, bk, bk);
        acc[wl][1] = make_float4(bk, bk, bk, bk);
    }

    const float* wrow  = wk_s + oc * 161;
    const float* cbase = xs + (oc >> 6) * 32 * CTW;

    for (int icl = 0; icl < 32; icl++) {
        const float* crow = cbase + icl * CTW;
        const float* wr   = wrow + icl * 5;
        #pragma unroll
        for (int kh = 0; kh < 5; kh++) {
            float wv = wr[kh];
            #pragma unroll
            for (int wl = 0; wl < KQ_W; wl++) {
                float4 c0 = *(const float4*)(crow + (wl + kh) * 8);
                float4 c1 = *(const float4*)(crow + (wl + kh) * 8 + 4);
                fma4(acc[wl][0], wv, c0);
                fma4(acc[wl][1], wv, c1);
            }
        }
    }

    #pragma unroll
    for (int wl = 0; wl < KQ_W; wl++) {
        int w = w0 + wl;
        if (oc < 128) {
            const float4* mp =
                (const float4*)&mask[(((size_t)b * 128 + oc) * W_ + w) * 8];
            float4 m0 = mp[0], m1 = mp[1];
            acc[wl][0].x += m0.x; acc[wl][0].y += m0.y;
            acc[wl][0].z += m0.z; acc[wl][0].w += m0.w;
            acc[wl][1].x += m1.x; acc[wl][1].y += m1.y;
            acc[wl][1].z += m1.z; acc[wl][1].w += m1.w;
            float* dst = &g_k[((size_t)b * W_ + w) * CP_ + oc * 8];
            ((float4*)dst)[0] = acc[wl][0];
            ((float4*)dst)[1] = acc[wl][1];
        } else {
            float* dst = &g_v[((size_t)b * W_ + w) * CP_ + (oc - 128) * 8];
            ((float4*)dst)[0] = acc[wl][0];
            ((float4*)dst)[1] = acc[wl][1];
        }
    }
}

// =====================================================================
// Kernel C: per-column (over w) max and 1/sum(exp) of g_k
// =====================================================================
__global__ __launch_bounds__(256, 4)
void kStat()
{
    __shared__ float sm[256];
    const int tid  = threadIdx.x;
    const int b    = blockIdx.y;
    const int i    = blockIdx.x * 128 + (tid & 127);
    const int half = tid >> 7;
    const float* col = &g_k[(size_t)b * W_ * CP_ + i];

    float mx = -3.4e38f;
    #pragma unroll 4
    for (int w = half; w < W_; w += 2)
        mx = fmaxf(mx, col[(size_t)w * CP_]);
    sm[tid] = mx;
    __syncthreads();
    mx = fmaxf(sm[tid & 127], sm[(tid & 127) + 128]);
    __syncthreads();

    float s = 0.f;
    #pragma unroll 4
    for (int w = half; w < W_; w += 2)
        s += __expf(col[(size_t)w * CP_] - mx);
    sm[tid] = s;
    __syncthreads();
    if (half == 0) {
        float tot = sm[tid] + sm[tid + 128];
        g_m [b * CP_ + i] = mx;
        g_rs[b * CP_ + i] = 1.f / tot;
    }
}

// =====================================================================
// Kernel C2: transpose K (with fused softmax exp) and V into [i][w] tf32
// =====================================================================
__global__ __launch_bounds__(256, 4)
void kTrans()
{
    __shared__ float sk[32][33];
    __shared__ float sv[32][33];
    const int tid = threadIdx.x;
    const int tx = tid & 31, ty = tid >> 5;
    const int b  = blockIdx.z;
    const int w0 = blockIdx.x * 32;
    const int i0 = blockIdx.y * 32;

    #pragma unroll
    for (int r = 0; r < 4; r++) {
        int w = w0 + ty + r * 8;
        size_t src = ((size_t)b * W_ + w) * CP_ + i0 + tx;
        sk[ty + r * 8][tx] = g_k[src];
        sv[ty + r * 8][tx] = g_v[src];
    }
    __syncthreads();

    #pragma unroll
    for (int r = 0; r < 4; r++) {
        int i = i0 + ty + r * 8;
        float mv = g_m [b * CP_ + i];
        float rv = g_rs[b * CP_ + i];
        size_t dst = ((size_t)b * CP_ + i) * W_ + w0 + tx;
        g_kt[dst] = to_tf32(__expf(sk[tx][ty + r * 8] - mv) * rv);
        g_vt[dst] = to_tf32(sv[tx][ty + r * 8]);
    }
}

// =====================================================================
// Kernel D/E: tf32 mma.sync GEMM, 128x128 tile, BK=16, 4-stage cp.async.
// =====================================================================
#define BKPAD   20
#define STG_SZ  (2 * 128 * BKPAD)   // floats per stage (A + B)

template<int KTOT, int MTOT, int EPI>
__global__ __launch_bounds__(256, 2)
void kGemmMMA()
{
    extern __shared__ float smemf[];
    const int tid  = threadIdx.x;
    const int lane = tid & 31, wid = tid >> 5;
    const int b  = blockIdx.z;
    const int n0 = blockIdx.x * 128;
    const int m0 = blockIdx.y * 128;

    const float* A  = (EPI == 0) ? g_vt : g_q;
    const float* Bp = (EPI == 0) ? g_kt : g_kv;

    const float* Ag = A  + (size_t)b * MTOT * KTOT + (size_t)m0 * KTOT;
    const float* Bg = Bp + (size_t)b * 1024 * KTOT + (size_t)n0 * KTOT;

    const uint32_t smem0 = smem_u32(smemf);
    const int NT = KTOT / 16;

    const int lr = tid >> 2, lc = (tid & 3) * 4;

    #pragma unroll
    for (int s = 0; s < 3; s++) {
        uint32_t sb = smem0 + s * STG_SZ * 4;
        const float* Agt = Ag + s * 16;
        const float* Bgt = Bg + s * 16;
        #pragma unroll
        for (int h = 0; h < 2; h++) {
            int r = lr + h * 64;
            uint32_t da = sb + (r * BKPAD + lc) * 4;
            asm volatile("cp.async.cg.shared.global [%0], [%1], 16;"
                         :: "r"(da), "l"(Agt + (size_t)r * KTOT + lc));
            uint32_t db = sb + (128 * BKPAD + r * BKPAD + lc) * 4;
            asm volatile("cp.async.cg.shared.global [%0], [%1], 16;"
                         :: "r"(db), "l"(Bgt + (size_t)r * KTOT + lc));
        }
        asm volatile("cp.async.commit_group;");
    }

    const int m_warp = (wid & 1) * 64;
    const int n_warp = (wid >> 1) * 32;

    float acc[4][4][4];
    #pragma unroll
    for (int mi = 0; mi < 4; mi++)
        #pragma unroll
        for (int nb = 0; nb < 4; nb++)
            #pragma unroll
            for (int e = 0; e < 4; e++) acc[mi][nb][e] = 0.f;

    const int a_row  = (lane < 16) ? lane : (lane - 16);
    const int a_koff = (lane < 16) ? 0 : 4;
    const int b_noff = (lane & 7) + ((lane >> 4) << 3);
    const int b_koff = ((lane >> 3) & 1) * 4;

    for (int t = 0; t < NT; t++) {
        asm volatile("cp.async.wait_group 2;");
        __syncthreads();

        if (t + 3 < NT) {
            uint32_t sb = smem0 + ((t + 3) & 3) * STG_SZ * 4;
            const float* Agt = Ag + (t + 3) * 16;
            const float* Bgt = Bg + (t + 3) * 16;
            #pragma unroll
            for (int h = 0; h < 2; h++) {
                int r = lr + h * 64;
                uint32_t da = sb + (r * BKPAD + lc) * 4;
                asm volatile("cp.async.cg.shared.global [%0], [%1], 16;"
                             :: "r"(da), "l"(Agt + (size_t)r * KTOT + lc));
                uint32_t db = sb + (128 * BKPAD + r * BKPAD + lc) * 4;
                asm volatile("cp.async.cg.shared.global [%0], [%1], 16;"
                             :: "r"(db), "l"(Bgt + (size_t)r * KTOT + lc));
            }
        }
        asm volatile("cp.async.commit_group;");

        const uint32_t As = smem0 + (t & 3) * STG_SZ * 4;
        const uint32_t Bs = As + 128 * BKPAD * 4;

        #pragma unroll
        for (int ks = 0; ks < 2; ks++) {
            const int k0 = ks * 8;
            uint32_t ar[4][4];
            #pragma unroll
            for (int mi = 0; mi < 4; mi++) {
                uint32_t addr = As +
                    ((m_warp + mi * 16 + a_row) * BKPAD + k0 + a_koff) * 4;
                LDSM4(ar[mi], addr);
            }
            uint32_t br[2][4];
            #pragma unroll
            for (int nb2 = 0; nb2 < 2; nb2++) {
                uint32_t addr = Bs +
                    ((n_warp + nb2 * 16 + b_noff) * BKPAD + k0 + b_koff) * 4;
                LDSM4(br[nb2], addr);
            }
            #pragma unroll
            for (int mi = 0; mi < 4; mi++)
                #pragma unroll
                for (int nb = 0; nb < 4; nb++)
                    mma_tf32(acc[mi][nb], ar[mi],
                             br[nb >> 1][(nb & 1) * 2],
                             br[nb >> 1][(nb & 1) * 2 + 1]);
        }
    }

    const int rg = lane >> 2;
    const int cg = (lane & 3) * 2;
    #pragma unroll
    for (int mi = 0; mi < 4; mi++) {
        const int row = m0 + m_warp + mi * 16 + rg;
        #pragma unroll
        for (int nb = 0; nb < 4; nb++) {
            const int col = n0 + n_warp + nb * 8 + cg;
            const float* c = acc[mi][nb];
            if (EPI == 0) {
                float2 lo = make_float2(to_tf32(c[0]), to_tf32(c[1]));
                float2 hi = make_float2(to_tf32(c[2]), to_tf32(c[3]));
                *(float2*)&g_kv[((size_t)b * CP_ + row)     * CP_ + col] = lo;
                *(float2*)&g_kv[((size_t)b * CP_ + row + 8) * CP_ + col] = hi;
            } else {
                const int oc = col >> 3, p = col & 7;
                float* base = &g_at[((size_t)b * MIDC_ + oc) * T_];
                *(float2*)&base[(size_t)row * 8 + p]       = make_float2(c[0], c[1]);
                *(float2*)&base[(size_t)(row + 8) * 8 + p] = make_float2(c[2], c[3]);
            }
        }
    }
}

// =====================================================================
// Kernel F: conv1d via tf32 mma.sync.
//   out[b][c][t] = bOut[c] + sum_{k=0..383} wOut[c][k] * at[b][k/3][t + k%3 - 1]
//   M=128 (c), N=128 t per block, K=384, BK=16, 24 chunks.
//   A (wOut) K-major [c][k] -> smem [m][BKPAD], ldmatrix fragments.
//   B gathered -> smem [k][NPAD=136], scalar-LDS fragments (documented layout).
//   Register double-buffered gmem->smem staging.
// =====================================================================
#define CNPAD 136
__global__ __launch_bounds__(256, 2)
void kConvMMA(const float* __restrict__ wOut, const float* __restrict__ bOut,
              float* __restrict__ out)
{
    __shared__ __align__(16) float As[2][128 * BKPAD];
    __shared__ __align__(16) float Bs[2][16 * CNPAD];

    const int tid  = threadIdx.x;
    const int lane = tid & 31, wid = tid >> 5;
    const int b  = blockIdx.y;
    const int t0 = blockIdx.x * 128;

    const float* Ab = &g_at[(size_t)b * MIDC_ * T_];

    // loader mapping
    const int alr = tid >> 1, alc = (tid & 1) * 8;      // A: row, k-offset (2xfloat4)
    const int bkl = tid >> 5;                           // B: k rows bkl, bkl+8
    const int bn4 = (tid & 31) * 4;                     // B: 4 consecutive t

    float4 aReg0, aReg1;
    float  bReg[2][4];

    // ---- preload chunk 0 ----
    {
        const float* ap = wOut + (size_t)alr * 384 + alc;
        aReg0 = *(const float4*)ap;
        aReg1 = *(const float4*)(ap + 4);
        #pragma unroll
        for (int h = 0; h < 2; h++) {
            int kg = bkl + h * 8;
            int m  = kg / 3, kt = kg - m * 3;
            const float* rowp = Ab + (size_t)m * T_;
            #pragma unroll
            for (int cc = 0; cc < 4; cc++) {
                int t = t0 + bn4 + cc + kt - 1;
                bReg[h][cc] = (t >= 0 && t < T_) ? __ldg(rowp + t) : 0.f;
            }
        }
    }

    const int m_warp = (wid & 1) * 64;
    const int n_warp = (wid >> 1) * 32;

    float acc[4][4][4];
    #pragma unroll
    for (int mi = 0; mi < 4; mi++)
        #pragma unroll
        for (int nb = 0; nb < 4; nb++)
            #pragma unroll
            for (int e = 0; e < 4; e++) acc[mi][nb][e] = 0.f;

    const int a_row  = (lane < 16) ? lane : (lane - 16);
    const int a_koff = (lane < 16) ? 0 : 4;
    const int b_k    = lane & 3;
    const int b_n    = lane >> 2;

    const uint32_t As0 = smem_u32(&As[0][0]);
    const uint32_t Bs0 = smem_u32(&Bs[0][0]);

    for (int ch = 0; ch < 24; ch++) {
        const int buf = ch & 1;
        // stage regs -> smem
        *(float4*)&As[buf][alr * BKPAD + alc]     = aReg0;
        *(float4*)&As[buf][alr * BKPAD + alc + 4] = aReg1;
        *(float4*)&Bs[buf][bkl * CNPAD + bn4]       = make_float4(bReg[0][0], bReg[0][1], bReg[0][2], bReg[0][3]);
        *(float4*)&Bs[buf][(bkl + 8) * CNPAD + bn4] = make_float4(bReg[1][0], bReg[1][1], bReg[1][2], bReg[1][3]);
        __syncthreads();

        // preload chunk ch+1
        if (ch < 23) {
            const float* ap = wOut + (size_t)alr * 384 + (ch + 1) * 16 + alc;
            aReg0 = *(const float4*)ap;
            aReg1 = *(const float4*)(ap + 4);
            #pragma unroll
            for (int h = 0; h < 2; h++) {
                int kg = (ch + 1) * 16 + bkl + h * 8;
                int m  = kg / 3, kt = kg - m * 3;
                const float* rowp = Ab + (size_t)m * T_;
                #pragma unroll
                for (int cc = 0; cc < 4; cc++) {
                    int t = t0 + bn4 + cc + kt - 1;
                    bReg[h][cc] = (t >= 0 && t < T_) ? __ldg(rowp + t) : 0.f;
                }
            }
        }

        const uint32_t Asb = As0 + buf * (128 * BKPAD * 4);
        const float*   Bsb = &Bs[buf][0];

        #pragma unroll
        for (int ks = 0; ks < 2; ks++) {
            const int k0 = ks * 8;
            uint32_t ar[4][4];
            #pragma unroll
            for (int mi = 0; mi < 4; mi++) {
                uint32_t addr = Asb +
                    ((m_warp + mi * 16 + a_row) * BKPAD + k0 + a_koff) * 4;
                LDSM4(ar[mi], addr);
            }
            #pragma unroll
            for (int nb = 0; nb < 4; nb++) {
                const int n = n_warp + nb * 8 + b_n;
                uint32_t b0 = __float_as_uint(to_tf32(Bsb[(k0 + b_k) * CNPAD + n]));
                uint32_t b1 = __float_as_uint(to_tf32(Bsb[(k0 + 4 + b_k) * CNPAD + n]));
                #pragma unroll
                for (int mi = 0; mi < 4; mi++)
                    mma_tf32(acc[mi][nb], ar[mi], b0, b1);
            }
        }
        __syncthreads();
    }
    (void)Bs0;

    // ---- epilogue with bias ----
    const int rg = lane >> 2;
    const int cg = (lane & 3) * 2;
    #pragma unroll
    for (int mi = 0; mi < 4; mi++) {
        const int row = m_warp + mi * 16 + rg;
        const float bi0 = __ldg(&bOut[row]);
        const float bi1 = __ldg(&bOut[row + 8]);
        float* r0 = out + ((size_t)b * 128 + row)     * T_ + t0;
        float* r1 = out + ((size_t)b * 128 + row + 8) * T_ + t0;
        #pragma unroll
        for (int nb = 0; nb < 4; nb++) {
            const int col = n_warp + nb * 8 + cg;
            const float* c = acc[mi][nb];
            *(float2*)(r0 + col) = make_float2(c[0] + bi0, c[1] + bi0);
            *(float2*)(r1 + col) = make_float2(c[2] + bi1, c[3] + bi1);
        }
    }
}

// =====================================================================
// launcher
// =====================================================================
extern "C" void kernel_launch(void* const* d_in, const int* in_sizes, int n_in,
                              void* d_out, int out_size)
{
    (void)in_sizes; (void)n_in; (void)out_size;
    const float* x    = (const float*)d_in[0];
    const float* cond = (const float*)d_in[1];
    const float* mask = (const float*)d_in[2];
    const float* wQ   = (const float*)d_in[3];
    const float* bQ   = (const float*)d_in[4];
    const float* wKV  = (const float*)d_in[5];
    const float* bKV  = (const float*)d_in[6];
    const float* wOut = (const float*)d_in[7];
    const float* bOut = (const float*)d_in[8];
    float* out = (float*)d_out;

    const size_t smA = (size_t)(128 * 161 + 128 * CTW + 8) * sizeof(float);
    const size_t smB = (size_t)(256 * 161 + 128 * CTW) * sizeof(float);
    const size_t smG = (size_t)4 * STG_SZ * sizeof(float);   // 80 KB
    cudaFuncSetAttribute(kQ,  cudaFuncAttributeMaxDynamicSharedMemorySize, (int)smA);
    cudaFuncSetAttribute(kKV, cudaFuncAttributeMaxDynamicSharedMemorySize, (int)smB);
    cudaFuncSetAttribute(kGemmMMA<2048, 1024, 0>,
                         cudaFuncAttributeMaxDynamicSharedMemorySize, (int)smG);
    cudaFuncSetAttribute(kGemmMMA<1024, 2048, 1>,
                         cudaFuncAttributeMaxDynamicSharedMemorySize, (int)smG);

    kQ   <<<dim3(W_ / KQ_W, B_), 256, smA>>>(cond, wQ, bQ);
    kKV  <<<dim3(W_ / KQ_W, B_), 256, smB>>>(x, mask, wKV, bKV);
    kStat<<<dim3(CP_ / 128, B_), 256>>>();
    kTrans<<<dim3(W_ / 32, CP_ / 32, B_), 256>>>();
    // GEMM1: D1[i][j] = sum_w vt[i][w] * kt[j][w]   (M=1024, N=1024, K=2048)
    kGemmMMA<2048, 1024, 0><<<dim3(CP_ / 128, CP_ / 128, B_), 256, smG>>>();
    // GEMM2: D2[w][i] = sum_j q[w][j] * kv[i][j]    (M=2048, N=1024, K=1024)
    kGemmMMA<1024, 2048, 1><<<dim3(CP_ / 128, W_ / 128, B_), 256, smG>>>();
    kConvMMA<<<dim3(T_ / 128, B_), 256>>>(wOut, bOut, out);
}

// round 5
// speedup vs baseline: 3.3263x; 1.7956x over previous
#include <cuda_runtime.h>
#include <cstdint>

// ---------------- problem constants ----------------
#define B_    16
#define C_    128
#define T_    16384
#define W_    2048      // wordnum = T/patch
#define P_    8
#define MIDC_ 128
#define CP_   1024      // MIDC * P

// ---------------- scratch (device globals; allocation-free rule) ----------------
__device__ float g_qr[(size_t)B_ * W_ * CP_];   // raw Q (pre-softmax) [b][w][i]
__device__ float g_q [(size_t)B_ * W_ * CP_];   // tf32 softmaxed Q    [b][w][i]
__device__ float g_kt[(size_t)B_ * CP_ * W_];   // K^T raw -> (in place) tf32 softmax(K)^T [b][i][w]
__device__ float g_vt[(size_t)B_ * CP_ * W_];   // tf32 V^T            [b][i][w]
__device__ float g_kv[(size_t)B_ * CP_ * CP_];  // tf32 kv_mat^T       [b][i][j]
__device__ float g_at[(size_t)B_ * MIDC_ * T_]; // attn out fp32       [b][m][t]

// ---------------- helpers ----------------
__device__ __forceinline__ uint32_t smem_u32(const void* p) {
    uint32_t a;
    asm("{ .reg .u64 t; cvta.to.shared.u64 t, %1; cvt.u32.u64 %0, t; }"
        : "=r"(a) : "l"(p));
    return a;
}

__device__ __forceinline__ float to_tf32(float x) {
    uint32_t u;
    asm("cvt.rna.tf32.f32 %0, %1;" : "=r"(u) : "f"(x));
    return __uint_as_float(u);
}

#define LDSM4(r, addr)                                                        \
    asm volatile("ldmatrix.sync.aligned.m8n8.x4.shared.b16 {%0,%1,%2,%3}, [%4];" \
        : "=r"((r)[0]), "=r"((r)[1]), "=r"((r)[2]), "=r"((r)[3]) : "r"(addr))

__device__ __forceinline__ void mma_tf32(float* c, const uint32_t* a,
                                         uint32_t b0, uint32_t b1) {
    asm volatile(
        "mma.sync.aligned.m16n8k8.row.col.f32.tf32.tf32.f32 "
        "{%0,%1,%2,%3}, {%4,%5,%6,%7}, {%8,%9}, {%0,%1,%2,%3};"
        : "+f"(c[0]), "+f"(c[1]), "+f"(c[2]), "+f"(c[3])
        : "r"(a[0]), "r"(a[1]), "r"(a[2]), "r"(a[3]), "r"(b0), "r"(b1));
}

// =====================================================================
// Kernel A/B: grouped 5-tap conv as tf32 MMA.
//   Per block: group g, 256 t (=32 w), batch b.
//   M = MOC oc of group (Q:32, KV:64), K = 160 (32 ic x 5 taps), N = 256.
//   B[k][n] = inp[b][g*32 + k/5][t0 + n + (k%5 - 2)*8]  (zero-padded)
//   Q epilogue: +bias, transpose -> g_qr [w][i'] rows (raw fp32).
//   KV epilogue: +bias (+mask for K groups 0,1), transpose -> [i][w] rows:
//     K -> g_kt raw fp32; V -> g_vt tf32.
// =====================================================================
#define CAPAD 172
#define CBPAD 260
#define CWPAD 33      // KV epilogue [i][w] pad
#define CIPAD 260     // Q  epilogue [w][i'] pad

template<int MOC, bool ISQ>
__global__ __launch_bounds__(256, 2)
void kConv(const float* __restrict__ inp, const float* __restrict__ wgt,
           const float* __restrict__ bias, const float* __restrict__ mask)
{
    extern __shared__ float sf[];
    float* As = sf;                       // MOC x CAPAD
    float* Bs = sf + MOC * CAPAD;         // 2 x 16 x CBPAD

    const int tid  = threadIdx.x;
    const int lane = tid & 31, wid = tid >> 5;
    const int t0 = blockIdx.x * 256;
    const int w0 = blockIdx.x * 32;
    const int g  = blockIdx.y;
    const int b  = blockIdx.z;

    const float* Irow = inp + ((size_t)b * 128 + g * 32) * T_;
    const float* Arow = wgt + (size_t)g * MOC * 160;

    // ---- load A (weights) once, tf32-rounded ----
    for (int idx = tid; idx < MOC * 40; idx += 256) {
        int row = idx / 40, c4 = idx - row * 40;
        float4 v = *(const float4*)(Arow + row * 160 + c4 * 4);
        v.x = to_tf32(v.x); v.y = to_tf32(v.y);
        v.z = to_tf32(v.z); v.w = to_tf32(v.w);
        *(float4*)&As[row * CAPAD + c4 * 4] = v;
    }

    // ---- B chunk loader (cp.async, zero-fill OOB) ----
    auto load_chunk = [&](int ch) {
        uint32_t bb = smem_u32(Bs + (ch & 1) * 16 * CBPAD);
        #pragma unroll
        for (int it = 0; it < 4; it++) {
            int idx = tid + it * 256;           // 0..1023 float4s
            int r = idx >> 6, c4 = (idx & 63) << 2;
            int k = ch * 16 + r;
            int ic = k / 5, kh = k - ic * 5;
            int t = t0 + c4 + (kh - 2) * 8;
            int tc = t < 0 ? 0 : (t > T_ - 4 ? T_ - 4 : t);
            int sz = (t >= 0 && t <= T_ - 4) ? 16 : 0;
            const float* src = Irow + (size_t)ic * T_ + tc;
            uint32_t dst = bb + (r * CBPAD + c4) * 4;
            asm volatile("cp.async.cg.shared.global [%0], [%1], 16, %2;"
                         :: "r"(dst), "l"(src), "r"(sz));
        }
        asm volatile("cp.async.commit_group;");
    };

    constexpr int MF = MOC / 16;
    float acc[MF][4][4];
    #pragma unroll
    for (int mi = 0; mi < MF; mi++)
        #pragma unroll
        for (int nb = 0; nb < 4; nb++)
            #pragma unroll
            for (int e = 0; e < 4; e++) acc[mi][nb][e] = 0.f;

    const int n_warp = wid * 32;
    const int a_row  = (lane < 16) ? lane : (lane - 16);
    const int a_koff = (lane < 16) ? 0 : 4;
    const int b_k    = lane & 3;
    const int b_n    = lane >> 2;
    const uint32_t As0 = smem_u32(As);

    load_chunk(0);
    __syncthreads();   // A smem ready too

    for (int ch = 0; ch < 10; ch++) {
        if (ch < 9) {
            load_chunk(ch + 1);
            asm volatile("cp.async.wait_group 1;");
        } else {
            asm volatile("cp.async.wait_group 0;");
        }
        __syncthreads();

        const float* Bb = Bs + (ch & 1) * 16 * CBPAD;
        #pragma unroll
        for (int ks = 0; ks < 2; ks++) {
            const int k0 = ks * 8;
            uint32_t ar[MF][4];
            #pragma unroll
            for (int mi = 0; mi < MF; mi++)
                LDSM4(ar[mi], As0 +
                    ((mi * 16 + a_row) * CAPAD + ch * 16 + k0 + a_koff) * 4);
            #pragma unroll
            for (int nb = 0; nb < 4; nb++) {
                const int n = n_warp + nb * 8 + b_n;
                uint32_t b0 = __float_as_uint(to_tf32(Bb[(k0 + b_k) * CBPAD + n]));
                uint32_t b1 = __float_as_uint(to_tf32(Bb[(k0 + 4 + b_k) * CBPAD + n]));
                #pragma unroll
                for (int mi = 0; mi < MF; mi++)
                    mma_tf32(acc[mi][nb], ar[mi], b0, b1);
            }
        }
        __syncthreads();
    }

    // ---- epilogue ----
    const int rg = lane >> 2;
    const int cg = (lane & 3) * 2;
    const float* bptr = bias + g * MOC;

    if (ISQ) {
        float* s2 = sf;    // [32 w][CIPAD] (reuses A+B space)
        #pragma unroll
        for (int mi = 0; mi < MF; mi++) {
            const int r0 = mi * 16 + rg, r1 = r0 + 8;
            const float bi0 = bptr[r0], bi1 = bptr[r1];
            #pragma unroll
            for (int nb = 0; nb < 4; nb++) {
                const int col = n_warp + nb * 8 + cg;
                const int w = col >> 3, p = col & 7;
                const float* c = acc[mi][nb];
                *(float2*)&s2[w * CIPAD + r0 * 8 + p] = make_float2(c[0] + bi0, c[1] + bi0);
                *(float2*)&s2[w * CIPAD + r1 * 8 + p] = make_float2(c[2] + bi1, c[3] + bi1);
            }
        }
        __syncthreads();
        const int w = tid >> 3, c64 = (tid & 7) * 32;
        float* dst = g_qr + ((size_t)b * W_ + w0 + w) * CP_ + g * 256 + c64;
        #pragma unroll
        for (int j = 0; j < 8; j++)
            *(float4*)(dst + j * 4) = *(const float4*)&s2[w * CIPAD + c64 + j * 4];
    } else {
        float* s2 = sf;    // [512 i][CWPAD]
        const bool isK = (g < 2);
        const float* mrow = isK ?
            (mask + ((size_t)b * 128 + g * 64) * (size_t)T_ + t0) : nullptr;
        #pragma unroll
        for (int mi = 0; mi < MF; mi++) {
            const int r0 = mi * 16 + rg, r1 = r0 + 8;
            const float bi0 = bptr[r0], bi1 = bptr[r1];
            #pragma unroll
            for (int nb = 0; nb < 4; nb++) {
                const int col = n_warp + nb * 8 + cg;
                const int w = col >> 3, p = col & 7;
                const float* c = acc[mi][nb];
                float2 m0 = make_float2(0.f, 0.f), m1 = m0;
                if (isK) {
                    m0 = *(const float2*)(mrow + (size_t)r0 * T_ + col);
                    m1 = *(const float2*)(mrow + (size_t)r1 * T_ + col);
                }
                s2[(r0 * 8 + p)     * CWPAD + w] = c[0] + bi0 + m0.x;
                s2[(r0 * 8 + p + 1) * CWPAD + w] = c[1] + bi0 + m0.y;
                s2[(r1 * 8 + p)     * CWPAD + w] = c[2] + bi1 + m1.x;
                s2[(r1 * 8 + p + 1) * CWPAD + w] = c[3] + bi1 + m1.y;
            }
        }
        __syncthreads();
        #pragma unroll
        for (int h = 0; h < 2; h++) {
            const int i = tid + h * 256;
            float* drow = (isK ? g_kt : g_vt) +
                ((size_t)b * CP_ + (size_t)(g & 1) * 512 + i) * W_ + w0;
            #pragma unroll
            for (int j = 0; j < 8; j++) {
                float4 v;
                v.x = s2[i * CWPAD + j * 4 + 0];
                v.y = s2[i * CWPAD + j * 4 + 1];
                v.z = s2[i * CWPAD + j * 4 + 2];
                v.w = s2[i * CWPAD + j * 4 + 3];
                if (!isK) {
                    v.x = to_tf32(v.x); v.y = to_tf32(v.y);
                    v.z = to_tf32(v.z); v.w = to_tf32(v.w);
                }
                *(float4*)(drow + j * 4) = v;
            }
        }
    }
}

// =====================================================================
// Kernel C: row softmax of g_qr (1024 per row) -> g_q tf32
// =====================================================================
__global__ __launch_bounds__(256, 4)
void kSoftQ()
{
    __shared__ float red[8];
    const int tid = threadIdx.x, lane = tid & 31, wrp = tid >> 5;
    const size_t off = ((size_t)blockIdx.y * W_ + blockIdx.x) * CP_;

    float4 v = *(const float4*)(g_qr + off + tid * 4);
    float mx = fmaxf(fmaxf(v.x, v.y), fmaxf(v.z, v.w));
    #pragma unroll
    for (int o = 16; o; o >>= 1)
        mx = fmaxf(mx, __shfl_xor_sync(0xffffffffu, mx, o));
    if (lane == 0) red[wrp] = mx;
    __syncthreads();
    float m = red[0];
    #pragma unroll
    for (int k = 1; k < 8; k++) m = fmaxf(m, red[k]);

    float4 e;
    e.x = __expf(v.x - m); e.y = __expf(v.y - m);
    e.z = __expf(v.z - m); e.w = __expf(v.w - m);
    float s = e.x + e.y + e.z + e.w;
    #pragma unroll
    for (int o = 16; o; o >>= 1)
        s += __shfl_xor_sync(0xffffffffu, s, o);
    __syncthreads();
    if (lane == 0) red[wrp] = s;
    __syncthreads();
    float tot = 0.f;
    #pragma unroll
    for (int k = 0; k < 8; k++) tot += red[k];
    float r = 1.f / tot;

    float4 o;
    o.x = to_tf32(e.x * r); o.y = to_tf32(e.y * r);
    o.z = to_tf32(e.z * r); o.w = to_tf32(e.w * r);
    *(float4*)(g_q + off + tid * 4) = o;
}

// =====================================================================
// Kernel D: per-row (i) softmax over w of g_kt (2048 per row), IN PLACE -> tf32
// =====================================================================
__global__ __launch_bounds__(256, 4)
void kStatK()
{
    __shared__ float red[8];
    const int tid = threadIdx.x, lane = tid & 31, wrp = tid >> 5;
    const size_t off = ((size_t)blockIdx.y * CP_ + blockIdx.x) * (size_t)W_;

    float4 v0 = *(const float4*)(g_kt + off + tid * 4);
    float4 v1 = *(const float4*)(g_kt + off + 1024 + tid * 4);
    float mx = fmaxf(fmaxf(fmaxf(v0.x, v0.y), fmaxf(v0.z, v0.w)),
                     fmaxf(fmaxf(v1.x, v1.y), fmaxf(v1.z, v1.w)));
    #pragma unroll
    for (int o = 16; o; o >>= 1)
        mx = fmaxf(mx, __shfl_xor_sync(0xffffffffu, mx, o));
    if (lane == 0) red[wrp] = mx;
    __syncthreads();
    float m = red[0];
    #pragma unroll
    for (int k = 1; k < 8; k++) m = fmaxf(m, red[k]);

    float4 e0, e1;
    e0.x = __expf(v0.x - m); e0.y = __expf(v0.y - m);
    e0.z = __expf(v0.z - m); e0.w = __expf(v0.w - m);
    e1.x = __expf(v1.x - m); e1.y = __expf(v1.y - m);
    e1.z = __expf(v1.z - m); e1.w = __expf(v1.w - m);
    float s = e0.x + e0.y + e0.z + e0.w + e1.x + e1.y + e1.z + e1.w;
    #pragma unroll
    for (int o = 16; o; o >>= 1)
        s += __shfl_xor_sync(0xffffffffu, s, o);
    __syncthreads();
    if (lane == 0) red[wrp] = s;
    __syncthreads();
    float tot = 0.f;
    #pragma unroll
    for (int k = 0; k < 8; k++) tot += red[k];
    float r = 1.f / tot;

    float4 o0, o1;
    o0.x = to_tf32(e0.x * r); o0.y = to_tf32(e0.y * r);
    o0.z = to_tf32(e0.z * r); o0.w = to_tf32(e0.w * r);
    o1.x = to_tf32(e1.x * r); o1.y = to_tf32(e1.y * r);
    o1.z = to_tf32(e1.z * r); o1.w = to_tf32(e1.w * r);
    *(float4*)(g_kt + off + tid * 4)        = o0;
    *(float4*)(g_kt + off + 1024 + tid * 4) = o1;
}

// =====================================================================
// Kernel E/F: tf32 mma.sync GEMM, 128x128 tile, BK=16, 4-stage cp.async.
//   EPI==0: D1[i][j] = sum_w vt[i][w]*kt[j][w]  -> g_kv (tf32, = kv_mat^T)
//   EPI==1: D2[w][i] = sum_j  q[w][j]*kv[i][j]  -> g_at scatter (fp32)
// =====================================================================
#define BKPAD   20
#define STG_SZ  (2 * 128 * BKPAD)

template<int KTOT, int MTOT, int EPI>
__global__ __launch_bounds__(256, 2)
void kGemmMMA()
{
    extern __shared__ float smemf[];
    const int tid  = threadIdx.x;
    const int lane = tid & 31, wid = tid >> 5;
    const int b  = blockIdx.z;
    const int n0 = blockIdx.x * 128;
    const int m0 = blockIdx.y * 128;

    const float* A  = (EPI == 0) ? g_vt : g_q;
    const float* Bp = (EPI == 0) ? g_kt : g_kv;

    const float* Ag = A  + (size_t)b * MTOT * KTOT + (size_t)m0 * KTOT;
    const float* Bg = Bp + (size_t)b * 1024 * KTOT + (size_t)n0 * KTOT;

    const uint32_t smem0 = smem_u32(smemf);
    const int NT = KTOT / 16;

    const int lr = tid >> 2, lc = (tid & 3) * 4;

    #pragma unroll
    for (int s = 0; s < 3; s++) {
        uint32_t sb = smem0 + s * STG_SZ * 4;
        const float* Agt = Ag + s * 16;
        const float* Bgt = Bg + s * 16;
        #pragma unroll
        for (int h = 0; h < 2; h++) {
            int r = lr + h * 64;
            uint32_t da = sb + (r * BKPAD + lc) * 4;
            asm volatile("cp.async.cg.shared.global [%0], [%1], 16;"
                         :: "r"(da), "l"(Agt + (size_t)r * KTOT + lc));
            uint32_t db = sb + (128 * BKPAD + r * BKPAD + lc) * 4;
            asm volatile("cp.async.cg.shared.global [%0], [%1], 16;"
                         :: "r"(db), "l"(Bgt + (size_t)r * KTOT + lc));
        }
        asm volatile("cp.async.commit_group;");
    }

    const int m_warp = (wid & 1) * 64;
    const int n_warp = (wid >> 1) * 32;

    float acc[4][4][4];
    #pragma unroll
    for (int mi = 0; mi < 4; mi++)
        #pragma unroll
        for (int nb = 0; nb < 4; nb++)
            #pragma unroll
            for (int e = 0; e < 4; e++) acc[mi][nb][e] = 0.f;

    const int a_row  = (lane < 16) ? lane : (lane - 16);
    const int a_koff = (lane < 16) ? 0 : 4;
    const int b_noff = (lane & 7) + ((lane >> 4) << 3);
    const int b_koff = ((lane >> 3) & 1) * 4;

    for (int t = 0; t < NT; t++) {
        asm volatile("cp.async.wait_group 2;");
        __syncthreads();

        if (t + 3 < NT) {
            uint32_t sb = smem0 + ((t + 3) & 3) * STG_SZ * 4;
            const float* Agt = Ag + (t + 3) * 16;
            const float* Bgt = Bg + (t + 3) * 16;
            #pragma unroll
            for (int h = 0; h < 2; h++) {
                int r = lr + h * 64;
                uint32_t da = sb + (r * BKPAD + lc) * 4;
                asm volatile("cp.async.cg.shared.global [%0], [%1], 16;"
                             :: "r"(da), "l"(Agt + (size_t)r * KTOT + lc));
                uint32_t db = sb + (128 * BKPAD + r * BKPAD + lc) * 4;
                asm volatile("cp.async.cg.shared.global [%0], [%1], 16;"
                             :: "r"(db), "l"(Bgt + (size_t)r * KTOT + lc));
            }
        }
        asm volatile("cp.async.commit_group;");

        const uint32_t As = smem0 + (t & 3) * STG_SZ * 4;
        const uint32_t Bs = As + 128 * BKPAD * 4;

        #pragma unroll
        for (int ks = 0; ks < 2; ks++) {
            const int k0 = ks * 8;
            uint32_t ar[4][4];
            #pragma unroll
            for (int mi = 0; mi < 4; mi++) {
                uint32_t addr = As +
                    ((m_warp + mi * 16 + a_row) * BKPAD + k0 + a_koff) * 4;
                LDSM4(ar[mi], addr);
            }
            uint32_t br[2][4];
            #pragma unroll
            for (int nb2 = 0; nb2 < 2; nb2++) {
                uint32_t addr = Bs +
                    ((n_warp + nb2 * 16 + b_noff) * BKPAD + k0 + b_koff) * 4;
                LDSM4(br[nb2], addr);
            }
            #pragma unroll
            for (int mi = 0; mi < 4; mi++)
                #pragma unroll
                for (int nb = 0; nb < 4; nb++)
                    mma_tf32(acc[mi][nb], ar[mi],
                             br[nb >> 1][(nb & 1) * 2],
                             br[nb >> 1][(nb & 1) * 2 + 1]);
        }
    }

    const int rg = lane >> 2;
    const int cg = (lane & 3) * 2;
    #pragma unroll
    for (int mi = 0; mi < 4; mi++) {
        const int row = m0 + m_warp + mi * 16 + rg;
        #pragma unroll
        for (int nb = 0; nb < 4; nb++) {
            const int col = n0 + n_warp + nb * 8 + cg;
            const float* c = acc[mi][nb];
            if (EPI == 0) {
                float2 lo = make_float2(to_tf32(c[0]), to_tf32(c[1]));
                float2 hi = make_float2(to_tf32(c[2]), to_tf32(c[3]));
                *(float2*)&g_kv[((size_t)b * CP_ + row)     * CP_ + col] = lo;
                *(float2*)&g_kv[((size_t)b * CP_ + row + 8) * CP_ + col] = hi;
            } else {
                const int oc = col >> 3, p = col & 7;
                float* base = &g_at[((size_t)b * MIDC_ + oc) * T_];
                *(float2*)&base[(size_t)row * 8 + p]       = make_float2(c[0], c[1]);
                *(float2*)&base[(size_t)(row + 8) * 8 + p] = make_float2(c[2], c[3]);
            }
        }
    }
}

// =====================================================================
// Kernel G: conv1d via tf32 mma.sync (M=128 c, N=128 t, K=384)
// =====================================================================
#define CNPAD 136
__global__ __launch_bounds__(256, 2)
void kConvMMA(const float* __restrict__ wOut, const float* __restrict__ bOut,
              float* __restrict__ out)
{
    __shared__ __align__(16) float As[2][128 * BKPAD];
    __shared__ __align__(16) float Bs[2][16 * CNPAD];

    const int tid  = threadIdx.x;
    const int lane = tid & 31, wid = tid >> 5;
    const int b  = blockIdx.y;
    const int t0 = blockIdx.x * 128;

    const float* Ab = &g_at[(size_t)b * MIDC_ * T_];

    const int alr = tid >> 1, alc = (tid & 1) * 8;
    const int bkl = tid >> 5;
    const int bn4 = (tid & 31) * 4;

    float4 aReg0, aReg1;
    float  bReg[2][4];

    {
        const float* ap = wOut + (size_t)alr * 384 + alc;
        aReg0 = *(const float4*)ap;
        aReg1 = *(const float4*)(ap + 4);
        #pragma unroll
        for (int h = 0; h < 2; h++) {
            int kg = bkl + h * 8;
            int m  = kg / 3, kt = kg - m * 3;
            const float* rowp = Ab + (size_t)m * T_;
            #pragma unroll
            for (int cc = 0; cc < 4; cc++) {
                int t = t0 + bn4 + cc + kt - 1;
                bReg[h][cc] = (t >= 0 && t < T_) ? __ldg(rowp + t) : 0.f;
            }
        }
    }

    const int m_warp = (wid & 1) * 64;
    const int n_warp = (wid >> 1) * 32;

    float acc[4][4][4];
    #pragma unroll
    for (int mi = 0; mi < 4; mi++)
        #pragma unroll
        for (int nb = 0; nb < 4; nb++)
            #pragma unroll
            for (int e = 0; e < 4; e++) acc[mi][nb][e] = 0.f;

    const int a_row  = (lane < 16) ? lane : (lane - 16);
    const int a_koff = (lane < 16) ? 0 : 4;
    const int b_k    = lane & 3;
    const int b_n    = lane >> 2;

    const uint32_t As0 = smem_u32(&As[0][0]);

    for (int ch = 0; ch < 24; ch++) {
        const int buf = ch & 1;
        *(float4*)&As[buf][alr * BKPAD + alc]     = aReg0;
        *(float4*)&As[buf][alr * BKPAD + alc + 4] = aReg1;
        *(float4*)&Bs[buf][bkl * CNPAD + bn4]       = make_float4(bReg[0][0], bReg[0][1], bReg[0][2], bReg[0][3]);
        *(float4*)&Bs[buf][(bkl + 8) * CNPAD + bn4] = make_float4(bReg[1][0], bReg[1][1], bReg[1][2], bReg[1][3]);
        __syncthreads();

        if (ch < 23) {
            const float* ap = wOut + (size_t)alr * 384 + (ch + 1) * 16 + alc;
            aReg0 = *(const float4*)ap;
            aReg1 = *(const float4*)(ap + 4);
            #pragma unroll
            for (int h = 0; h < 2; h++) {
                int kg = (ch + 1) * 16 + bkl + h * 8;
                int m  = kg / 3, kt = kg - m * 3;
                const float* rowp = Ab + (size_t)m * T_;
                #pragma unroll
                for (int cc = 0; cc < 4; cc++) {
                    int t = t0 + bn4 + cc + kt - 1;
                    bReg[h][cc] = (t >= 0 && t < T_) ? __ldg(rowp + t) : 0.f;
                }
            }
        }

        const uint32_t Asb = As0 + buf * (128 * BKPAD * 4);
        const float*   Bsb = &Bs[buf][0];

        #pragma unroll
        for (int ks = 0; ks < 2; ks++) {
            const int k0 = ks * 8;
            uint32_t ar[4][4];
            #pragma unroll
            for (int mi = 0; mi < 4; mi++) {
                uint32_t addr = Asb +
                    ((m_warp + mi * 16 + a_row) * BKPAD + k0 + a_koff) * 4;
                LDSM4(ar[mi], addr);
            }
            #pragma unroll
            for (int nb = 0; nb < 4; nb++) {
                const int n = n_warp + nb * 8 + b_n;
                uint32_t b0 = __float_as_uint(to_tf32(Bsb[(k0 + b_k) * CNPAD + n]));
                uint32_t b1 = __float_as_uint(to_tf32(Bsb[(k0 + 4 + b_k) * CNPAD + n]));
                #pragma unroll
                for (int mi = 0; mi < 4; mi++)
                    mma_tf32(acc[mi][nb], ar[mi], b0, b1);
            }
        }
        __syncthreads();
    }

    const int rg = lane >> 2;
    const int cg = (lane & 3) * 2;
    #pragma unroll
    for (int mi = 0; mi < 4; mi++) {
        const int row = m_warp + mi * 16 + rg;
        const float bi0 = __ldg(&bOut[row]);
        const float bi1 = __ldg(&bOut[row + 8]);
        float* r0 = out + ((size_t)b * 128 + row)     * T_ + t0;
        float* r1 = out + ((size_t)b * 128 + row + 8) * T_ + t0;
        #pragma unroll
        for (int nb = 0; nb < 4; nb++) {
            const int col = n_warp + nb * 8 + cg;
            const float* c = acc[mi][nb];
            *(float2*)(r0 + col) = make_float2(c[0] + bi0, c[1] + bi0);
            *(float2*)(r1 + col) = make_float2(c[2] + bi1, c[3] + bi1);
        }
    }
}

// =====================================================================
// launcher
// =====================================================================
extern "C" void kernel_launch(void* const* d_in, const int* in_sizes, int n_in,
                              void* d_out, int out_size)
{
    (void)in_sizes; (void)n_in; (void)out_size;
    const float* x    = (const float*)d_in[0];
    const float* cond = (const float*)d_in[1];
    const float* mask = (const float*)d_in[2];
    const float* wQ   = (const float*)d_in[3];
    const float* bQ   = (const float*)d_in[4];
    const float* wKV  = (const float*)d_in[5];
    const float* bKV  = (const float*)d_in[6];
    const float* wOut = (const float*)d_in[7];
    const float* bOut = (const float*)d_in[8];
    float* out = (float*)d_out;

    const size_t smQ  = (size_t)(32 * CAPAD + 2 * 16 * CBPAD) * sizeof(float);  // ~55 KB
    const size_t smKV = (size_t)(64 * CAPAD + 2 * 16 * CBPAD) * sizeof(float);  // ~77 KB
    const size_t smG  = (size_t)4 * STG_SZ * sizeof(float);                     // 80 KB
    cudaFuncSetAttribute(kConv<32, true>,
                         cudaFuncAttributeMaxDynamicSharedMemorySize, (int)smQ);
    cudaFuncSetAttribute(kConv<64, false>,
                         cudaFuncAttributeMaxDynamicSharedMemorySize, (int)smKV);
    cudaFuncSetAttribute(kGemmMMA<2048, 1024, 0>,
                         cudaFuncAttributeMaxDynamicSharedMemorySize, (int)smG);
    cudaFuncSetAttribute(kGemmMMA<1024, 2048, 1>,
                         cudaFuncAttributeMaxDynamicSharedMemorySize, (int)smG);

    // grouped convs (MMA): grid (t-tiles, groups, batch)
    kConv<32, true ><<<dim3(T_ / 256, 4, B_), 256, smQ >>>(cond, wQ,  bQ,  nullptr);
    kConv<64, false><<<dim3(T_ / 256, 4, B_), 256, smKV>>>(x,    wKV, bKV, mask);
    kSoftQ<<<dim3(W_, B_), 256>>>();
    kStatK<<<dim3(CP_, B_), 256>>>();
    // GEMM1: D1[i][j] = sum_w vt[i][w] * kt[j][w]   (M=1024, N=1024, K=2048)
    kGemmMMA<2048, 1024, 0><<<dim3(CP_ / 128, CP_ / 128, B_), 256, smG>>>();
    // GEMM2: D2[w][i] = sum_j q[w][j] * kv[i][j]    (M=2048, N=1024, K=1024)
    kGemmMMA<1024, 2048, 1><<<dim3(CP_ / 128, W_ / 128, B_), 256, smG>>>();
    kConvMMA<<<dim3(T_ / 128, B_), 256>>>(wOut, bOut, out);
}